// round 14
// baseline (speedup 1.0000x reference)
#include <cuda_runtime.h>
#include <cuda_bf16.h>
#include <cstdint>
#include <cstddef>

typedef unsigned long long ull;

// Problem constants
#define TT 512
#define BB 32
#define DD 512
#define HH 512

// ---------------------------------------------------------------------------
// Scratch (device globals — no allocations allowed)
// ---------------------------------------------------------------------------
__device__ float g_gi[(size_t)2 * 1536 * (TT * BB)];
__device__ float g_y0[(size_t)TT * BB * 1024];
// hidden state bf16 hi/lo ping-pong: [2 buf][2 dir][32 b][512 k]  (round-8)
__device__ __nv_bfloat16 g_hh[2 * 2 * BB * HH];
__device__ __nv_bfloat16 g_hl[2 * 2 * BB * HH];
// per-producer dataflow flags: F[dir][jb] = steps published
__device__ unsigned g_flags[2 * 64];
__device__ __nv_bfloat16 g_wh[2][1536 * 1024];
__device__ __nv_bfloat16 g_wl[2][1536 * 1024];
__device__ __nv_bfloat16 g_xh[(size_t)16384 * 1024];
__device__ __nv_bfloat16 g_xl[(size_t)16384 * 1024];

// ---------------------------------------------------------------------------
// MMA / ldmatrix macros
// ---------------------------------------------------------------------------
#define MMA_BF16(d, a, b) \
    asm volatile("mma.sync.aligned.m16n8k16.row.col.f32.bf16.bf16.f32 " \
        "{%0,%1,%2,%3}, {%4,%5,%6,%7}, {%8,%9}, {%0,%1,%2,%3};" \
        : "+f"((d)[0]), "+f"((d)[1]), "+f"((d)[2]), "+f"((d)[3]) \
        : "r"((a)[0]), "r"((a)[1]), "r"((a)[2]), "r"((a)[3]), \
          "r"((b)[0]), "r"((b)[1]))

#define LDSM_X4(r, addr) \
    asm volatile("ldmatrix.sync.aligned.m8n8.x4.shared.b16 {%0,%1,%2,%3}, [%4];" \
        : "=r"((r)[0]), "=r"((r)[1]), "=r"((r)[2]), "=r"((r)[3]) : "r"(addr))

#define LDSM_X2(r, addr) \
    asm volatile("ldmatrix.sync.aligned.m8n8.x2.shared.b16 {%0,%1}, [%2];" \
        : "=r"((r)[0]), "=r"((r)[1]) : "r"(addr))

#define CP_ASYNC16(dst, src) \
    asm volatile("cp.async.cg.shared.global [%0], [%1], 16;" \
        :: "r"(dst), "l"(src) : "memory")

// ---------------------------------------------------------------------------
// split fp32 -> bf16 hi + bf16 lo
// ---------------------------------------------------------------------------
__global__ void split_bf16(const float* __restrict__ x,
                           __nv_bfloat16* __restrict__ hi,
                           __nv_bfloat16* __restrict__ lo, size_t n)
{
    size_t i = (size_t)blockIdx.x * blockDim.x + threadIdx.x;
    size_t stride = (size_t)gridDim.x * blockDim.x;
    for (; i < n; i += stride) {
        float v = x[i];
        __nv_bfloat16 h = __float2bfloat16(v);
        hi[i] = h;
        lo[i] = __float2bfloat16(v - __bfloat162float(h));
    }
}

// ---------------------------------------------------------------------------
// bf16 mma.sync GEMM, 3-pass hi/lo split, 2-stage cp.async pipelined
// (round-13 passing: 292us, tensor=49%).
// ---------------------------------------------------------------------------
#define SKW 40
#define TILE_E (128 * SKW)
#define STAGE_E (4 * TILE_E)
#define GEMM_SMEM (2 * STAGE_E * 2)

__global__ void __launch_bounds__(256)
gemm_bf16_mma(const __nv_bfloat16* __restrict__ Wh,
              const __nv_bfloat16* __restrict__ Wl,
              const __nv_bfloat16* __restrict__ Xh,
              const __nv_bfloat16* __restrict__ Xl,
              const float* __restrict__ bias,
              float* __restrict__ C, int K, int ldc)
{
    extern __shared__ __align__(16) __nv_bfloat16 sm[];

    const int tid  = threadIdx.x;
    const int wid  = tid >> 5;
    const int lane = tid & 31;
    const int m0   = blockIdx.x * 128;
    const int n0   = blockIdx.y * 128;
    const int wn   = wid >> 2;
    const int wm   = wid & 3;

    float acc[4][4][4];
#pragma unroll
    for (int nt = 0; nt < 4; nt++)
#pragma unroll
        for (int mt = 0; mt < 4; mt++)
#pragma unroll
            for (int e = 0; e < 4; e++) acc[nt][mt][e] = 0.0f;

    const int a_off = (wn * 64 + (lane & 15)) * SKW + (lane >> 4) * 8;
    const int b_off = (wm * 32 + (lane & 7)) * SKW + ((lane >> 3) & 1) * 8;
    const uint32_t aWh0 = (uint32_t)__cvta_generic_to_shared(sm + a_off);
    const uint32_t aWl0 = aWh0 + TILE_E * 2;
    const uint32_t aXh0 = (uint32_t)__cvta_generic_to_shared(sm + 2 * TILE_E + b_off);
    const uint32_t aXl0 = aXh0 + TILE_E * 2;

    const int srow0 = tid >> 2, sc0 = tid & 3;
    const int srow1 = (tid + 256) >> 2, sc1 = (tid + 256) & 3;
    const uint32_t d00 = (uint32_t)__cvta_generic_to_shared(sm + srow0 * SKW + sc0 * 8);
    const uint32_t d01 = (uint32_t)__cvta_generic_to_shared(sm + srow1 * SKW + sc1 * 8);

    const int nk = K >> 5;

    {
        const size_t gw0 = (size_t)(n0 + srow0) * K + sc0 * 8;
        const size_t gw1 = (size_t)(n0 + srow1) * K + sc1 * 8;
        const size_t gx0 = (size_t)(m0 + srow0) * K + sc0 * 8;
        const size_t gx1 = (size_t)(m0 + srow1) * K + sc1 * 8;
        CP_ASYNC16(d00,                  Wh + gw0);
        CP_ASYNC16(d00 + TILE_E * 2,     Wl + gw0);
        CP_ASYNC16(d00 + 2 * TILE_E * 2, Xh + gx0);
        CP_ASYNC16(d00 + 3 * TILE_E * 2, Xl + gx0);
        CP_ASYNC16(d01,                  Wh + gw1);
        CP_ASYNC16(d01 + TILE_E * 2,     Wl + gw1);
        CP_ASYNC16(d01 + 2 * TILE_E * 2, Xh + gx1);
        CP_ASYNC16(d01 + 3 * TILE_E * 2, Xl + gx1);
        asm volatile("cp.async.commit_group;" ::: "memory");
    }

    for (int kt = 0; kt < nk; kt++) {
        const uint32_t stB = (uint32_t)((kt & 1) * STAGE_E * 2);

        if (kt + 1 < nk) {
            const uint32_t nsB = (uint32_t)(((kt + 1) & 1) * STAGE_E * 2);
            const int k0n = (kt + 1) * 32;
            const size_t gw0 = (size_t)(n0 + srow0) * K + k0n + sc0 * 8;
            const size_t gw1 = (size_t)(n0 + srow1) * K + k0n + sc1 * 8;
            const size_t gx0 = (size_t)(m0 + srow0) * K + k0n + sc0 * 8;
            const size_t gx1 = (size_t)(m0 + srow1) * K + k0n + sc1 * 8;
            CP_ASYNC16(d00 + nsB,                  Wh + gw0);
            CP_ASYNC16(d00 + nsB + TILE_E * 2,     Wl + gw0);
            CP_ASYNC16(d00 + nsB + 2 * TILE_E * 2, Xh + gx0);
            CP_ASYNC16(d00 + nsB + 3 * TILE_E * 2, Xl + gx0);
            CP_ASYNC16(d01 + nsB,                  Wh + gw1);
            CP_ASYNC16(d01 + nsB + TILE_E * 2,     Wl + gw1);
            CP_ASYNC16(d01 + nsB + 2 * TILE_E * 2, Xh + gx1);
            CP_ASYNC16(d01 + nsB + 3 * TILE_E * 2, Xl + gx1);
            asm volatile("cp.async.commit_group;" ::: "memory");
            asm volatile("cp.async.wait_group 1;" ::: "memory");
        } else {
            asm volatile("cp.async.wait_group 0;" ::: "memory");
        }
        __syncthreads();

#pragma unroll
        for (int kk = 0; kk < 2; kk++) {
            const uint32_t koff = stB + (uint32_t)(kk * 32);
            uint32_t ah[4][4], al[4][4], bh[4][2], bl[4][2];
#pragma unroll
            for (int nt = 0; nt < 4; nt++) {
                const uint32_t ro = (uint32_t)(nt * 16 * SKW * 2);
                LDSM_X4(ah[nt], aWh0 + ro + koff);
                LDSM_X4(al[nt], aWl0 + ro + koff);
            }
#pragma unroll
            for (int mt = 0; mt < 4; mt++) {
                const uint32_t ro = (uint32_t)(mt * 8 * SKW * 2);
                LDSM_X2(bh[mt], aXh0 + ro + koff);
                LDSM_X2(bl[mt], aXl0 + ro + koff);
            }
#pragma unroll
            for (int nt = 0; nt < 4; nt++)
#pragma unroll
                for (int mt = 0; mt < 4; mt++) {
                    MMA_BF16(acc[nt][mt], ah[nt], bh[mt]);
                    MMA_BF16(acc[nt][mt], ah[nt], bl[mt]);
                    MMA_BF16(acc[nt][mt], al[nt], bh[mt]);
                }
        }
        __syncthreads();
    }

    const int r0 = lane >> 2;
    const int c0 = (lane & 3) * 2;
#pragma unroll
    for (int nt = 0; nt < 4; nt++) {
        const int nbase = n0 + wn * 64 + nt * 16;
        const float b0 = bias[nbase + r0];
        const float b1 = bias[nbase + 8 + r0];
#pragma unroll
        for (int mt = 0; mt < 4; mt++) {
            const int mbase = m0 + wm * 32 + mt * 8;
            float2 v0, v1;
            v0.x = acc[nt][mt][0] + b0; v0.y = acc[nt][mt][1] + b0;
            v1.x = acc[nt][mt][2] + b1; v1.y = acc[nt][mt][3] + b1;
            *(float2*)(C + (size_t)(nbase + r0) * ldc + mbase + c0) = v0;
            *(float2*)(C + (size_t)(nbase + 8 + r0) * ldc + mbase + c0) = v1;
        }
    }
}

// ---------------------------------------------------------------------------
// Persistent MMA GRU v6: round-8 engine + PER-WARP DATAFLOW FLAGS.
// No global barrier. Warp w consumes h columns [128w,128w+128) = producers
// jb in [16w,16w+16); it polls exactly those 16 flags (lanes 0-15, one
// coalesced 64B line) and stages its own K-quarter (no intra-CTA sync
// between stage and MMA — warp reads only what it wrote).
// 2-slot ring safety: a CTA at step s observed all flags >= s, so every
// CTA completed step s-1 INCLUDING its staging reads of slot (s-1)&1 —
// the only slot step-s publishes overwrite.
// Grid: 128 CTAs = 2 dirs x 64 j-blocks (8 j). 128 threads (4 warps).
// SMEM: A 66,560 B + red 12,288 B = 78,848 B.
// ---------------------------------------------------------------------------
#define RS 520
#define A_ELEMS (32 * RS)
#define RED_OFF (2 * A_ELEMS * 2)
#define MMA_SMEM (RED_OFF + 4 * 2 * 3 * 32 * 16)

__global__ __launch_bounds__(128, 1)
void gru_layer_mma(const float* __restrict__ gi,
                   const float* __restrict__ Whh_f,
                   const float* __restrict__ Whh_b,
                   const float* __restrict__ bhh_f,
                   const float* __restrict__ bhh_b,
                   __nv_bfloat16* __restrict__ hh,   // [2][2][32][512]
                   __nv_bfloat16* __restrict__ hl,
                   unsigned* __restrict__ flags,     // [2][64], zeroed
                   float* __restrict__ y,
                   float* __restrict__ hid)
{
    extern __shared__ __align__(16) char smraw[];
    __nv_bfloat16* sAh = (__nv_bfloat16*)smraw;
    __nv_bfloat16* sAl = sAh + A_ELEMS;
    float* red = (float*)(smraw + RED_OFF);

    __nv_bfloat16* sWh = sAh;
    __nv_bfloat16* sWl = sAh + 24 * RS;

    const int tid  = threadIdx.x;
    const int wid  = tid >> 5;
    const int lane = tid & 31;
    const int dir  = (int)(blockIdx.x >> 6);
    const int jb   = (int)(blockIdx.x & 63);
    const int j0   = jb * 8;

    const float* Whh = dir ? Whh_b : Whh_f;
    const float* bhh = dir ? bhh_b : bhh_f;

    // ---- stage Whh tile (24 rows x 512) hi/lo split into smem ----
    for (int i = tid; i < 24 * 128; i += 128) {
        int rr = i >> 7;
        int c4 = i & 127;
        int g = rr >> 3, jj = rr & 7;
        int grow = g * 512 + j0 + jj;
        float4 v = *(const float4*)(Whh + (size_t)grow * 512 + c4 * 4);
        int so = rr * RS + c4 * 4;
        float vv[4] = {v.x, v.y, v.z, v.w};
#pragma unroll
        for (int e = 0; e < 4; e++) {
            __nv_bfloat16 h = __float2bfloat16(vv[e]);
            sWh[so + e] = h;
            sWl[so + e] = __float2bfloat16(vv[e] - __bfloat162float(h));
        }
    }
    __syncthreads();

    // ---- hoist B fragments into registers: [8 kt][3 g][hi/lo][2] ----
    uint32_t bh[8][3][2], bl[8][3][2];
    {
        const int brow = (lane & 7);
        const int bcol = ((lane >> 3) & 1) * 8;
#pragma unroll
        for (int kt = 0; kt < 8; kt++) {
            const uint32_t koff = (uint32_t)((wid * 8 + kt) * 16 * 2);
#pragma unroll
            for (int g = 0; g < 3; g++) {
                uint32_t ah_ = (uint32_t)__cvta_generic_to_shared(
                    sWh + (g * 8 + brow) * RS + bcol) + koff;
                uint32_t al_ = (uint32_t)__cvta_generic_to_shared(
                    sWl + (g * 8 + brow) * RS + bcol) + koff;
                LDSM_X2(bh[kt][g], ah_);
                LDSM_X2(bl[kt][g], al_);
            }
        }
    }
    __syncthreads();   // W region dead; A buffers may now be written

    uint32_t aAh[2], aAl[2];
#pragma unroll
    for (int mt = 0; mt < 2; mt++) {
        const int arow = mt * 16 + (lane & 15);
        const int acol = (lane >> 4) * 8;
        aAh[mt] = (uint32_t)__cvta_generic_to_shared(sAh + arow * RS + acol);
        aAl[mt] = (uint32_t)__cvta_generic_to_shared(sAl + arow * RS + acol);
    }

    const int gm  = wid;
    const int b0  = gm * 16 + (lane >> 2);
    const int b1  = b0 + 8;
    const int j   = j0 + 2 * (lane & 3);

    const float br0 = bhh[j],          br1 = bhh[j + 1];
    const float bz0 = bhh[HH + j],     bz1 = bhh[HH + j + 1];
    const float bn0 = bhh[2 * HH + j], bn1 = bhh[2 * HH + j + 1];

    const float* gb[3][2];
#pragma unroll
    for (int g = 0; g < 3; g++) {
#pragma unroll
        for (int q = 0; q < 2; q++)
            gb[g][q] = gi + ((size_t)dir * 1536 + g * 512 + j + q) * (size_t)(TT * BB);
    }

    unsigned* Fd = flags + dir * 64;
    unsigned* myflag = Fd + jb;
    unsigned* pollp = Fd + (wid << 4) + (lane & 15);   // this warp's 16 producers

    float hp[4] = {0.0f, 0.0f, 0.0f, 0.0f};

    for (int s = 0; s < TT; s++) {
        const int t = dir ? (TT - 1 - s) : s;

        // ---- gi prefetch (warps 0/1), independent of flags ----
        float pre[3][4];
        if (wid < 2) {
#pragma unroll
            for (int g = 0; g < 3; g++) {
                pre[g][0] = __ldcg(gb[g][0] + t * BB + b0);
                pre[g][1] = __ldcg(gb[g][1] + t * BB + b0);
                pre[g][2] = __ldcg(gb[g][0] + t * BB + b1);
                pre[g][3] = __ldcg(gb[g][1] + t * BB + b1);
            }
        }

        // ---- per-warp poll: exactly this warp's 16 producers ----
        if (s > 0) {
            const unsigned target = (unsigned)s;
            for (;;) {
                unsigned v = target;
                if (lane < 16) {
                    asm volatile("ld.acquire.gpu.global.u32 %0, [%1];"
                                 : "=r"(v) : "l"(pollp) : "memory");
                }
                if (__all_sync(0xFFFFFFFFu, v >= target)) break;
            }
        }

        // ---- per-warp stage of OWN K-quarter (cols [128w,128w+128)) ----
        // No syncthreads: this warp is sole writer AND sole reader.
        {
            const size_t sb = ((size_t)(s & 1) * 2 + dir) * (BB * HH);
            const __nv_bfloat16* srch = hh + sb + wid * 128;
            const __nv_bfloat16* srcl = hl + sb + wid * 128;
            const int smbase = wid * 128;
#pragma unroll
            for (int i = 0; i < 16; i++) {
                const int idx = lane + i * 32;        // 0..511
                const int row = idx >> 4;             // 0..31
                const int ch  = idx & 15;             // 16B chunk in quarter
                uint4 vh = __ldcg((const uint4*)(srch + (size_t)row * HH + ch * 8));
                uint4 vl = __ldcg((const uint4*)(srcl + (size_t)row * HH + ch * 8));
                *(uint4*)(sAh + row * RS + smbase + ch * 8) = vh;
                *(uint4*)(sAl + row * RS + smbase + ch * 8) = vl;
            }
        }
        __syncwarp();

        // ---- MMA over this warp's 8 ktiles ----
        float acc[2][3][4];
#pragma unroll
        for (int mt = 0; mt < 2; mt++)
#pragma unroll
            for (int g = 0; g < 3; g++)
#pragma unroll
                for (int e = 0; e < 4; e++) acc[mt][g][e] = 0.0f;

#pragma unroll
        for (int kt = 0; kt < 8; kt++) {
            const uint32_t koff = (uint32_t)((wid * 8 + kt) * 32);
#pragma unroll
            for (int mt = 0; mt < 2; mt++) {
                uint32_t ah[4], al[4];
                LDSM_X4(ah, aAh[mt] + koff);
                LDSM_X4(al, aAl[mt] + koff);
#pragma unroll
                for (int g = 0; g < 3; g++) {
                    MMA_BF16(acc[mt][g], ah, bh[kt][g]);
                    MMA_BF16(acc[mt][g], ah, bl[kt][g]);
                    MMA_BF16(acc[mt][g], al, bh[kt][g]);
                }
            }
        }

        // ---- cross-warp K-reduction via smem ----
#pragma unroll
        for (int mt = 0; mt < 2; mt++)
#pragma unroll
            for (int g = 0; g < 3; g++) {
                float4 v;
                v.x = acc[mt][g][0]; v.y = acc[mt][g][1];
                v.z = acc[mt][g][2]; v.w = acc[mt][g][3];
                *(float4*)(red + (((wid * 2 + mt) * 3 + g) * 32 + lane) * 4) = v;
            }
        __syncthreads();

        // ---- gates + h publish (warps 0/1, m-tile = wid) ----
        float hn[4];
        if (wid < 2) {
            float tot[3][4];
#pragma unroll
            for (int g = 0; g < 3; g++) {
                float4 v0 = *(float4*)(red + (((0 * 2 + gm) * 3 + g) * 32 + lane) * 4);
                float4 v1 = *(float4*)(red + (((1 * 2 + gm) * 3 + g) * 32 + lane) * 4);
                float4 v2 = *(float4*)(red + (((2 * 2 + gm) * 3 + g) * 32 + lane) * 4);
                float4 v3 = *(float4*)(red + (((3 * 2 + gm) * 3 + g) * 32 + lane) * 4);
                tot[g][0] = ((v0.x + v1.x) + (v2.x + v3.x));
                tot[g][1] = ((v0.y + v1.y) + (v2.y + v3.y));
                tot[g][2] = ((v0.z + v1.z) + (v2.z + v3.z));
                tot[g][3] = ((v0.w + v1.w) + (v2.w + v3.w));
            }

            const float brj[2] = {br0, br1}, bzj[2] = {bz0, bz1}, bnj[2] = {bn0, bn1};
#pragma unroll
            for (int c = 0; c < 4; c++) {
                const int q = c & 1;
                const float ar = tot[0][c] + brj[q];
                const float az = tot[1][c] + bzj[q];
                const float an = tot[2][c] + bnj[q];
                const float r = 1.0f / (1.0f + expf(-(pre[0][c] + ar)));
                const float z = 1.0f / (1.0f + expf(-(pre[1][c] + az)));
                const float n = tanhf(pre[2][c] + r * an);
                hn[c] = (1.0f - z) * n + z * hp[c];
                hp[c] = hn[c];
            }

            // publish h (bf16 hi/lo, ping-pong slot (s+1)&1)
            const size_t ob = ((size_t)((s + 1) & 1) * 2 + dir) * (BB * HH);
            __nv_bfloat162 h2, l2;
            h2.x = __float2bfloat16(hn[0]);
            h2.y = __float2bfloat16(hn[1]);
            l2.x = __float2bfloat16(hn[0] - __bfloat162float(h2.x));
            l2.y = __float2bfloat16(hn[1] - __bfloat162float(h2.y));
            *(__nv_bfloat162*)(hh + ob + (size_t)b0 * HH + j) = h2;
            *(__nv_bfloat162*)(hl + ob + (size_t)b0 * HH + j) = l2;
            h2.x = __float2bfloat16(hn[2]);
            h2.y = __float2bfloat16(hn[3]);
            l2.x = __float2bfloat16(hn[2] - __bfloat162float(h2.x));
            l2.y = __float2bfloat16(hn[3] - __bfloat162float(h2.y));
            *(__nv_bfloat162*)(hh + ob + (size_t)b1 * HH + j) = h2;
            *(__nv_bfloat162*)(hl + ob + (size_t)b1 * HH + j) = l2;
        }

        // ---- release own flag (all publishes done CTA-wide) ----
        __syncthreads();
        if (tid == 0) {
            __threadfence();
            asm volatile("st.release.gpu.global.u32 [%0], %1;"
                         :: "l"(myflag), "r"((unsigned)(s + 1)) : "memory");
        }

        // off-critical-path y/hid stores (never read cross-CTA)
        if (wid < 2) {
            float2 y2;
            y2.x = hn[0]; y2.y = hn[1];
            *(float2*)(y + ((size_t)t * BB + b0) * 1024 + (size_t)dir * HH + j) = y2;
            y2.x = hn[2]; y2.y = hn[3];
            *(float2*)(y + ((size_t)t * BB + b1) * 1024 + (size_t)dir * HH + j) = y2;
            if (s == TT - 1) {
                float2 q2;
                q2.x = hn[0]; q2.y = hn[1];
                *(float2*)(hid + ((size_t)dir * BB + b0) * HH + j) = q2;
                q2.x = hn[2]; q2.y = hn[3];
                *(float2*)(hid + ((size_t)dir * BB + b1) * HH + j) = q2;
            }
        }
    }
}

// ---------------------------------------------------------------------------
// Launch
// ---------------------------------------------------------------------------
extern "C" void kernel_launch(void* const* d_in, const int* in_sizes, int n_in,
                              void* d_out, int out_size)
{
    (void)in_sizes; (void)n_in; (void)out_size;

    const float* x     = (const float*)d_in[0];
    const float* Wih0f = (const float*)d_in[1];
    const float* Whh0f = (const float*)d_in[2];
    const float* bih0f = (const float*)d_in[3];
    const float* bhh0f = (const float*)d_in[4];
    const float* Wih0b = (const float*)d_in[5];
    const float* Whh0b = (const float*)d_in[6];
    const float* bih0b = (const float*)d_in[7];
    const float* bhh0b = (const float*)d_in[8];
    const float* Wih1f = (const float*)d_in[9];
    const float* Whh1f = (const float*)d_in[10];
    const float* bih1f = (const float*)d_in[11];
    const float* bhh1f = (const float*)d_in[12];
    const float* Wih1b = (const float*)d_in[13];
    const float* Whh1b = (const float*)d_in[14];
    const float* bih1b = (const float*)d_in[15];
    const float* bhh1b = (const float*)d_in[16];

    float* out = (float*)d_out;
    const size_t Y_ELEMS = (size_t)TT * BB * 1024;
    float* hid0 = out + Y_ELEMS;
    float* hid1 = out + Y_ELEMS + 2 * BB * HH;

    float* gi = nullptr; cudaGetSymbolAddress((void**)&gi, g_gi);
    float* y0 = nullptr; cudaGetSymbolAddress((void**)&y0, g_y0);
    __nv_bfloat16* hh = nullptr; cudaGetSymbolAddress((void**)&hh, g_hh);
    __nv_bfloat16* hl = nullptr; cudaGetSymbolAddress((void**)&hl, g_hl);
    unsigned* flags = nullptr; cudaGetSymbolAddress((void**)&flags, g_flags);
    __nv_bfloat16* wh = nullptr; cudaGetSymbolAddress((void**)&wh, g_wh);
    __nv_bfloat16* wl = nullptr; cudaGetSymbolAddress((void**)&wl, g_wl);
    __nv_bfloat16* xh = nullptr; cudaGetSymbolAddress((void**)&xh, g_xh);
    __nv_bfloat16* xl = nullptr; cudaGetSymbolAddress((void**)&xl, g_xl);

    cudaFuncSetAttribute(gru_layer_mma,
                         cudaFuncAttributeMaxDynamicSharedMemorySize, MMA_SMEM);
    cudaFuncSetAttribute(gemm_bf16_mma,
                         cudaFuncAttributeMaxDynamicSharedMemorySize, GEMM_SMEM);

    const size_t M = (size_t)TT * BB;            // 16384
    const size_t DIROFF = (size_t)1536 * M;
    const size_t WSLAB = (size_t)1536 * 1024;
    const dim3 ggrid(128, 12);
    const size_t HBYTES = (size_t)2 * 2 * BB * HH * sizeof(__nv_bfloat16);

    // ---------------- layer 0 (K = 512) ----------------
    split_bf16<<<512, 256>>>(Wih0f, wh,          wl,          (size_t)1536 * DD);
    split_bf16<<<512, 256>>>(Wih0b, wh + WSLAB,  wl + WSLAB,  (size_t)1536 * DD);
    split_bf16<<<1024, 256>>>(x,    xh,          xl,          M * DD);

    gemm_bf16_mma<<<ggrid, 256, GEMM_SMEM>>>(wh,         wl,         xh, xl, bih0f,
                                             gi,          DD, (int)M);
    gemm_bf16_mma<<<ggrid, 256, GEMM_SMEM>>>(wh + WSLAB, wl + WSLAB, xh, xl, bih0b,
                                             gi + DIROFF, DD, (int)M);

    cudaMemsetAsync(hh, 0, HBYTES);
    cudaMemsetAsync(hl, 0, HBYTES);
    cudaMemsetAsync(flags, 0, 2 * 64 * sizeof(unsigned));

    gru_layer_mma<<<128, 128, MMA_SMEM>>>(
        gi, Whh0f, Whh0b, bhh0f, bhh0b, hh, hl, flags, y0, hid0);

    // ---------------- layer 1 (K = 1024) ----------------
    split_bf16<<<512, 256>>>(Wih1f, wh,          wl,          (size_t)1536 * 1024);
    split_bf16<<<512, 256>>>(Wih1b, wh + WSLAB,  wl + WSLAB,  (size_t)1536 * 1024);
    split_bf16<<<1024, 256>>>(y0,   xh,          xl,          M * 1024);

    gemm_bf16_mma<<<ggrid, 256, GEMM_SMEM>>>(wh,         wl,         xh, xl, bih1f,
                                             gi,          1024, (int)M);
    gemm_bf16_mma<<<ggrid, 256, GEMM_SMEM>>>(wh + WSLAB, wl + WSLAB, xh, xl, bih1b,
                                             gi + DIROFF, 1024, (int)M);

    cudaMemsetAsync(hh, 0, HBYTES);
    cudaMemsetAsync(hl, 0, HBYTES);
    cudaMemsetAsync(flags, 0, 2 * 64 * sizeof(unsigned));

    gru_layer_mma<<<128, 128, MMA_SMEM>>>(
        gi, Whh1f, Whh1b, bhh1f, bhh1b, hh, hl, flags, out, hid1);
}

// round 15
// speedup vs baseline: 1.7134x; 1.7134x over previous
#include <cuda_runtime.h>
#include <cuda_bf16.h>
#include <cuda_fp16.h>
#include <cstdint>
#include <cstddef>

typedef unsigned long long ull;

// Problem constants
#define TT 512
#define BB 32
#define DD 512
#define HH 512

// ---------------------------------------------------------------------------
// Scratch (device globals — no allocations allowed)
// ---------------------------------------------------------------------------
__device__ float g_gi[(size_t)2 * 1536 * (TT * BB)];
// hidden state fp16 ping-pong: [2 buf][2 dir][32 b][512 k]
__device__ __half g_hf[2 * 2 * BB * HH];
__device__ unsigned g_cnt[2];
__device__ unsigned g_flag[2];
__device__ __nv_bfloat16 g_wh[2][1536 * 1024];
__device__ __nv_bfloat16 g_wl[2][1536 * 1024];
__device__ __nv_bfloat16 g_xh[(size_t)16384 * 1024];
__device__ __nv_bfloat16 g_xl[(size_t)16384 * 1024];

// ---------------------------------------------------------------------------
// MMA / ldmatrix macros
// ---------------------------------------------------------------------------
#define MMA_BF16(d, a, b) \
    asm volatile("mma.sync.aligned.m16n8k16.row.col.f32.bf16.bf16.f32 " \
        "{%0,%1,%2,%3}, {%4,%5,%6,%7}, {%8,%9}, {%0,%1,%2,%3};" \
        : "+f"((d)[0]), "+f"((d)[1]), "+f"((d)[2]), "+f"((d)[3]) \
        : "r"((a)[0]), "r"((a)[1]), "r"((a)[2]), "r"((a)[3]), \
          "r"((b)[0]), "r"((b)[1]))

#define MMA_F16(d, a, b) \
    asm volatile("mma.sync.aligned.m16n8k16.row.col.f32.f16.f16.f32 " \
        "{%0,%1,%2,%3}, {%4,%5,%6,%7}, {%8,%9}, {%0,%1,%2,%3};" \
        : "+f"((d)[0]), "+f"((d)[1]), "+f"((d)[2]), "+f"((d)[3]) \
        : "r"((a)[0]), "r"((a)[1]), "r"((a)[2]), "r"((a)[3]), \
          "r"((b)[0]), "r"((b)[1]))

#define LDSM_X4(r, addr) \
    asm volatile("ldmatrix.sync.aligned.m8n8.x4.shared.b16 {%0,%1,%2,%3}, [%4];" \
        : "=r"((r)[0]), "=r"((r)[1]), "=r"((r)[2]), "=r"((r)[3]) : "r"(addr))

#define LDSM_X2(r, addr) \
    asm volatile("ldmatrix.sync.aligned.m8n8.x2.shared.b16 {%0,%1}, [%2];" \
        : "=r"((r)[0]), "=r"((r)[1]) : "r"(addr))

#define CP_ASYNC16(dst, src) \
    asm volatile("cp.async.cg.shared.global [%0], [%1], 16;" \
        :: "r"(dst), "l"(src) : "memory")

// ---------------------------------------------------------------------------
// split fp32 -> bf16 hi + bf16 lo
// ---------------------------------------------------------------------------
__global__ void split_bf16(const float* __restrict__ x,
                           __nv_bfloat16* __restrict__ hi,
                           __nv_bfloat16* __restrict__ lo, size_t n)
{
    size_t i = (size_t)blockIdx.x * blockDim.x + threadIdx.x;
    size_t stride = (size_t)gridDim.x * blockDim.x;
    for (; i < n; i += stride) {
        float v = x[i];
        __nv_bfloat16 h = __float2bfloat16(v);
        hi[i] = h;
        lo[i] = __float2bfloat16(v - __bfloat162float(h));
    }
}

// ---------------------------------------------------------------------------
// bf16 mma.sync GEMM, 3-pass hi/lo split, 2-stage cp.async (round-13 proven).
// ---------------------------------------------------------------------------
#define SKW 40
#define TILE_E (128 * SKW)
#define STAGE_E (4 * TILE_E)
#define GEMM_SMEM (2 * STAGE_E * 2)

__global__ void __launch_bounds__(256)
gemm_bf16_mma(const __nv_bfloat16* __restrict__ Wh,
              const __nv_bfloat16* __restrict__ Wl,
              const __nv_bfloat16* __restrict__ Xh,
              const __nv_bfloat16* __restrict__ Xl,
              const float* __restrict__ bias,
              float* __restrict__ C, int K, int ldc)
{
    extern __shared__ __align__(16) __nv_bfloat16 sm[];

    const int tid  = threadIdx.x;
    const int wid  = tid >> 5;
    const int lane = tid & 31;
    const int m0   = blockIdx.x * 128;
    const int n0   = blockIdx.y * 128;
    const int wn   = wid >> 2;
    const int wm   = wid & 3;

    float acc[4][4][4];
#pragma unroll
    for (int nt = 0; nt < 4; nt++)
#pragma unroll
        for (int mt = 0; mt < 4; mt++)
#pragma unroll
            for (int e = 0; e < 4; e++) acc[nt][mt][e] = 0.0f;

    const int a_off = (wn * 64 + (lane & 15)) * SKW + (lane >> 4) * 8;
    const int b_off = (wm * 32 + (lane & 7)) * SKW + ((lane >> 3) & 1) * 8;
    const uint32_t aWh0 = (uint32_t)__cvta_generic_to_shared(sm + a_off);
    const uint32_t aWl0 = aWh0 + TILE_E * 2;
    const uint32_t aXh0 = (uint32_t)__cvta_generic_to_shared(sm + 2 * TILE_E + b_off);
    const uint32_t aXl0 = aXh0 + TILE_E * 2;

    const int srow0 = tid >> 2, sc0 = tid & 3;
    const int srow1 = (tid + 256) >> 2, sc1 = (tid + 256) & 3;
    const uint32_t d00 = (uint32_t)__cvta_generic_to_shared(sm + srow0 * SKW + sc0 * 8);
    const uint32_t d01 = (uint32_t)__cvta_generic_to_shared(sm + srow1 * SKW + sc1 * 8);

    const int nk = K >> 5;

    {
        const size_t gw0 = (size_t)(n0 + srow0) * K + sc0 * 8;
        const size_t gw1 = (size_t)(n0 + srow1) * K + sc1 * 8;
        const size_t gx0 = (size_t)(m0 + srow0) * K + sc0 * 8;
        const size_t gx1 = (size_t)(m0 + srow1) * K + sc1 * 8;
        CP_ASYNC16(d00,                  Wh + gw0);
        CP_ASYNC16(d00 + TILE_E * 2,     Wl + gw0);
        CP_ASYNC16(d00 + 2 * TILE_E * 2, Xh + gx0);
        CP_ASYNC16(d00 + 3 * TILE_E * 2, Xl + gx0);
        CP_ASYNC16(d01,                  Wh + gw1);
        CP_ASYNC16(d01 + TILE_E * 2,     Wl + gw1);
        CP_ASYNC16(d01 + 2 * TILE_E * 2, Xh + gx1);
        CP_ASYNC16(d01 + 3 * TILE_E * 2, Xl + gx1);
        asm volatile("cp.async.commit_group;" ::: "memory");
    }

    for (int kt = 0; kt < nk; kt++) {
        const uint32_t stB = (uint32_t)((kt & 1) * STAGE_E * 2);

        if (kt + 1 < nk) {
            const uint32_t nsB = (uint32_t)(((kt + 1) & 1) * STAGE_E * 2);
            const int k0n = (kt + 1) * 32;
            const size_t gw0 = (size_t)(n0 + srow0) * K + k0n + sc0 * 8;
            const size_t gw1 = (size_t)(n0 + srow1) * K + k0n + sc1 * 8;
            const size_t gx0 = (size_t)(m0 + srow0) * K + k0n + sc0 * 8;
            const size_t gx1 = (size_t)(m0 + srow1) * K + k0n + sc1 * 8;
            CP_ASYNC16(d00 + nsB,                  Wh + gw0);
            CP_ASYNC16(d00 + nsB + TILE_E * 2,     Wl + gw0);
            CP_ASYNC16(d00 + nsB + 2 * TILE_E * 2, Xh + gx0);
            CP_ASYNC16(d00 + nsB + 3 * TILE_E * 2, Xl + gx0);
            CP_ASYNC16(d01 + nsB,                  Wh + gw1);
            CP_ASYNC16(d01 + nsB + TILE_E * 2,     Wl + gw1);
            CP_ASYNC16(d01 + nsB + 2 * TILE_E * 2, Xh + gx1);
            CP_ASYNC16(d01 + nsB + 3 * TILE_E * 2, Xl + gx1);
            asm volatile("cp.async.commit_group;" ::: "memory");
            asm volatile("cp.async.wait_group 1;" ::: "memory");
        } else {
            asm volatile("cp.async.wait_group 0;" ::: "memory");
        }
        __syncthreads();

#pragma unroll
        for (int kk = 0; kk < 2; kk++) {
            const uint32_t koff = stB + (uint32_t)(kk * 32);
            uint32_t ah[4][4], al[4][4], bh[4][2], bl[4][2];
#pragma unroll
            for (int nt = 0; nt < 4; nt++) {
                const uint32_t ro = (uint32_t)(nt * 16 * SKW * 2);
                LDSM_X4(ah[nt], aWh0 + ro + koff);
                LDSM_X4(al[nt], aWl0 + ro + koff);
            }
#pragma unroll
            for (int mt = 0; mt < 4; mt++) {
                const uint32_t ro = (uint32_t)(mt * 8 * SKW * 2);
                LDSM_X2(bh[mt], aXh0 + ro + koff);
                LDSM_X2(bl[mt], aXl0 + ro + koff);
            }
#pragma unroll
            for (int nt = 0; nt < 4; nt++)
#pragma unroll
                for (int mt = 0; mt < 4; mt++) {
                    MMA_BF16(acc[nt][mt], ah[nt], bh[mt]);
                    MMA_BF16(acc[nt][mt], ah[nt], bl[mt]);
                    MMA_BF16(acc[nt][mt], al[nt], bh[mt]);
                }
        }
        __syncthreads();
    }

    const int r0 = lane >> 2;
    const int c0 = (lane & 3) * 2;
#pragma unroll
    for (int nt = 0; nt < 4; nt++) {
        const int nbase = n0 + wn * 64 + nt * 16;
        const float b0 = bias[nbase + r0];
        const float b1 = bias[nbase + 8 + r0];
#pragma unroll
        for (int mt = 0; mt < 4; mt++) {
            const int mbase = m0 + wm * 32 + mt * 8;
            float2 v0, v1;
            v0.x = acc[nt][mt][0] + b0; v0.y = acc[nt][mt][1] + b0;
            v1.x = acc[nt][mt][2] + b1; v1.y = acc[nt][mt][3] + b1;
            *(float2*)(C + (size_t)(nbase + r0) * ldc + mbase + c0) = v0;
            *(float2*)(C + (size_t)(nbase + 8 + r0) * ldc + mbase + c0) = v1;
        }
    }
}

// ---------------------------------------------------------------------------
// Persistent MMA GRU v7: round-13 structure + global barrier (PROVEN), but
// h carried in SINGLE fp16 (|h| <= 1 always => fp16 rel err ~2^-11), and
// Whh in fp16 => ONE MMA pass instead of three. Per-warp work: 16 LDSM.x4,
// 48 MMA, 32 KB h staging (halved). Layer 0 writes bf16 hi/lo X directly
// (xq/xl non-null) so the big y0 split kernel is eliminated.
// Grid: 128 CTAs = 2 dirs x 64 j-blocks (8 j). 128 threads (4 warps).
// SMEM: A(fp16) 33,280 B + red 12,288 B = 45,568 B.
// ---------------------------------------------------------------------------
#define RS 520
#define NCD 64
#define A_ELEMS (32 * RS)                 // fp16 elems in A buffer
#define RED_OFF (A_ELEMS * 2)             // bytes
#define MMA_SMEM (RED_OFF + 4 * 2 * 3 * 32 * 16)

__global__ __launch_bounds__(128, 1)
void gru_layer_mma(const float* __restrict__ gi,
                   const float* __restrict__ Whh_f,
                   const float* __restrict__ Whh_b,
                   const float* __restrict__ bhh_f,
                   const float* __restrict__ bhh_b,
                   __half* __restrict__ hf,          // [2][2][32][512]
                   unsigned* __restrict__ cnt,
                   unsigned* __restrict__ flag,
                   float* __restrict__ y,            // fp32 out (layer 1) or unused
                   __nv_bfloat16* __restrict__ xq,   // layer 0: X hi out (or null)
                   __nv_bfloat16* __restrict__ xl,   // layer 0: X lo out
                   int xldc,                         // X row stride (1024)
                   float* __restrict__ hid)          // [2][B][H]
{
    extern __shared__ __align__(16) char smraw[];
    __half* sA  = (__half*)smraw;                    // [32][RS]
    float* red = (float*)(smraw + RED_OFF);

    __half* sW = sA;                                 // W init aliases A region

    const int tid  = threadIdx.x;
    const int wid  = tid >> 5;
    const int lane = tid & 31;
    const int dir  = (int)(blockIdx.x >> 6);
    const int j0   = (int)(blockIdx.x & 63) * 8;

    const float* Whh = dir ? Whh_b : Whh_f;
    const float* bhh = dir ? bhh_b : bhh_f;

    // ---- stage Whh tile (24 rows x 512) fp16 into smem ----
    for (int i = tid; i < 24 * 128; i += 128) {
        int rr = i >> 7;
        int c4 = i & 127;
        int g = rr >> 3, jj = rr & 7;
        int grow = g * 512 + j0 + jj;
        float4 v = *(const float4*)(Whh + (size_t)grow * 512 + c4 * 4);
        int so = rr * RS + c4 * 4;
        sW[so + 0] = __float2half(v.x);
        sW[so + 1] = __float2half(v.y);
        sW[so + 2] = __float2half(v.z);
        sW[so + 3] = __float2half(v.w);
    }
    __syncthreads();

    // ---- hoist B fragments into registers: [8 kt][3 g][2] ----
    uint32_t bf[8][3][2];
    {
        const int brow = (lane & 7);
        const int bcol = ((lane >> 3) & 1) * 8;
#pragma unroll
        for (int kt = 0; kt < 8; kt++) {
            const uint32_t koff = (uint32_t)((wid * 8 + kt) * 32);
#pragma unroll
            for (int g = 0; g < 3; g++) {
                uint32_t ad = (uint32_t)__cvta_generic_to_shared(
                    sW + (g * 8 + brow) * RS + bcol) + koff;
                LDSM_X2(bf[kt][g], ad);
            }
        }
    }
    __syncthreads();   // W region dead; A buffer may now be written

    uint32_t aA[2];
#pragma unroll
    for (int mt = 0; mt < 2; mt++) {
        const int arow = mt * 16 + (lane & 15);
        const int acol = (lane >> 4) * 8;
        aA[mt] = (uint32_t)__cvta_generic_to_shared(sA + arow * RS + acol);
    }

    const int gm  = wid;
    const int b0  = gm * 16 + (lane >> 2);
    const int b1  = b0 + 8;
    const int j   = j0 + 2 * (lane & 3);

    const float br0 = bhh[j],          br1 = bhh[j + 1];
    const float bz0 = bhh[HH + j],     bz1 = bhh[HH + j + 1];
    const float bn0 = bhh[2 * HH + j], bn1 = bhh[2 * HH + j + 1];

    const float* gb[3][2];
#pragma unroll
    for (int g = 0; g < 3; g++) {
#pragma unroll
        for (int q = 0; q < 2; q++)
            gb[g][q] = gi + ((size_t)dir * 1536 + g * 512 + j + q) * (size_t)(TT * BB);
    }

    unsigned* mycnt  = cnt + dir;
    unsigned* myflag = flag + dir;

    float hp[4] = {0.0f, 0.0f, 0.0f, 0.0f};

    for (int s = 0; s < TT; s++) {
        const int t = dir ? (TT - 1 - s) : s;

        // ---- stage h fp16 for this step: 32 rows x 512 = 2048 uint4 ----
        {
            const uint4* src = (const uint4*)(hf + ((size_t)(s & 1) * 2 + dir) * (BB * HH));
#pragma unroll
            for (int i = 0; i < 16; i++) {
                int idx = tid + i * 128;
                int row = idx >> 6;
                int c8  = idx & 63;
                uint4 v = __ldcg(src + idx);
                *(uint4*)(sA + row * RS + c8 * 8) = v;
            }
        }
        __syncthreads();

        // ---- gi prefetch (warps 0/1) ----
        float pre[3][4];
        if (wid < 2) {
#pragma unroll
            for (int g = 0; g < 3; g++) {
                pre[g][0] = __ldcg(gb[g][0] + t * BB + b0);
                pre[g][1] = __ldcg(gb[g][1] + t * BB + b0);
                pre[g][2] = __ldcg(gb[g][0] + t * BB + b1);
                pre[g][3] = __ldcg(gb[g][1] + t * BB + b1);
            }
        }

        // ---- MMA over this warp's 8 ktiles (single fp16 pass) ----
        float acc[2][3][4];
#pragma unroll
        for (int mt = 0; mt < 2; mt++)
#pragma unroll
            for (int g = 0; g < 3; g++)
#pragma unroll
                for (int e = 0; e < 4; e++) acc[mt][g][e] = 0.0f;

#pragma unroll
        for (int kt = 0; kt < 8; kt++) {
            const uint32_t koff = (uint32_t)((wid * 8 + kt) * 32);
#pragma unroll
            for (int mt = 0; mt < 2; mt++) {
                uint32_t ah[4];
                LDSM_X4(ah, aA[mt] + koff);
#pragma unroll
                for (int g = 0; g < 3; g++) {
                    MMA_F16(acc[mt][g], ah, bf[kt][g]);
                }
            }
        }

        // ---- cross-warp K-reduction via smem ----
#pragma unroll
        for (int mt = 0; mt < 2; mt++)
#pragma unroll
            for (int g = 0; g < 3; g++) {
                float4 v;
                v.x = acc[mt][g][0]; v.y = acc[mt][g][1];
                v.z = acc[mt][g][2]; v.w = acc[mt][g][3];
                *(float4*)(red + (((wid * 2 + mt) * 3 + g) * 32 + lane) * 4) = v;
            }
        __syncthreads();

        // ---- gates + h publish (warps 0/1, m-tile = wid) ----
        float hn[4];
        if (wid < 2) {
            float tot[3][4];
#pragma unroll
            for (int g = 0; g < 3; g++) {
                float4 v0 = *(float4*)(red + (((0 * 2 + gm) * 3 + g) * 32 + lane) * 4);
                float4 v1 = *(float4*)(red + (((1 * 2 + gm) * 3 + g) * 32 + lane) * 4);
                float4 v2 = *(float4*)(red + (((2 * 2 + gm) * 3 + g) * 32 + lane) * 4);
                float4 v3 = *(float4*)(red + (((3 * 2 + gm) * 3 + g) * 32 + lane) * 4);
                tot[g][0] = ((v0.x + v1.x) + (v2.x + v3.x));
                tot[g][1] = ((v0.y + v1.y) + (v2.y + v3.y));
                tot[g][2] = ((v0.z + v1.z) + (v2.z + v3.z));
                tot[g][3] = ((v0.w + v1.w) + (v2.w + v3.w));
            }

            const float brj[2] = {br0, br1}, bzj[2] = {bz0, bz1}, bnj[2] = {bn0, bn1};
#pragma unroll
            for (int c = 0; c < 4; c++) {
                const int q = c & 1;
                const float ar = tot[0][c] + brj[q];
                const float az = tot[1][c] + bzj[q];
                const float an = tot[2][c] + bnj[q];
                const float r = 1.0f / (1.0f + expf(-(pre[0][c] + ar)));
                const float z = 1.0f / (1.0f + expf(-(pre[1][c] + az)));
                const float n = tanhf(pre[2][c] + r * an);
                hn[c] = (1.0f - z) * n + z * hp[c];
                hp[c] = hn[c];
            }

            // publish h (fp16, ping-pong slot (s+1)&1) — critical path
            const size_t ob = ((size_t)((s + 1) & 1) * 2 + dir) * (BB * HH);
            *(__half2*)(hf + ob + (size_t)b0 * HH + j) =
                __floats2half2_rn(hn[0], hn[1]);
            *(__half2*)(hf + ob + (size_t)b1 * HH + j) =
                __floats2half2_rn(hn[2], hn[3]);
        }

        // ---- per-direction global barrier (proven) ----
        __syncthreads();
        if (tid == 0) {
            __threadfence();
            const unsigned target = (unsigned)(NCD * (s + 1));
            unsigned arrived = atomicAdd(mycnt, 1u) + 1u;
            if (arrived == target) {
                asm volatile("st.release.gpu.global.u32 [%0], %1;"
                             :: "l"(myflag), "r"((unsigned)(s + 1)) : "memory");
            }
        }

        // off-critical-path output stores while tid0 arrives/spins
        if (wid < 2) {
            if (xq) {
                // layer 0: write bf16 hi/lo X for the layer-1 GEMM
                const size_t xb0 = ((size_t)t * BB + b0) * xldc + (size_t)dir * HH + j;
                const size_t xb1 = ((size_t)t * BB + b1) * xldc + (size_t)dir * HH + j;
                __nv_bfloat162 h2, l2;
                h2.x = __float2bfloat16(hn[0]);
                h2.y = __float2bfloat16(hn[1]);
                l2.x = __float2bfloat16(hn[0] - __bfloat162float(h2.x));
                l2.y = __float2bfloat16(hn[1] - __bfloat162float(h2.y));
                *(__nv_bfloat162*)(xq + xb0) = h2;
                *(__nv_bfloat162*)(xl + xb0) = l2;
                h2.x = __float2bfloat16(hn[2]);
                h2.y = __float2bfloat16(hn[3]);
                l2.x = __float2bfloat16(hn[2] - __bfloat162float(h2.x));
                l2.y = __float2bfloat16(hn[3] - __bfloat162float(h2.y));
                *(__nv_bfloat162*)(xq + xb1) = h2;
                *(__nv_bfloat162*)(xl + xb1) = l2;
            } else {
                float2 y2;
                y2.x = hn[0]; y2.y = hn[1];
                *(float2*)(y + ((size_t)t * BB + b0) * 1024 + (size_t)dir * HH + j) = y2;
                y2.x = hn[2]; y2.y = hn[3];
                *(float2*)(y + ((size_t)t * BB + b1) * 1024 + (size_t)dir * HH + j) = y2;
            }
            if (s == TT - 1) {
                float2 q2;
                q2.x = hn[0]; q2.y = hn[1];
                *(float2*)(hid + ((size_t)dir * BB + b0) * HH + j) = q2;
                q2.x = hn[2]; q2.y = hn[3];
                *(float2*)(hid + ((size_t)dir * BB + b1) * HH + j) = q2;
            }
        }

        if (tid == 0) {
            unsigned v;
            do {
                asm volatile("ld.acquire.gpu.global.u32 %0, [%1];"
                             : "=r"(v) : "l"(myflag) : "memory");
            } while (v < (unsigned)(s + 1));
            __threadfence();
        }
        __syncthreads();
    }
}

// ---------------------------------------------------------------------------
// Launch
// ---------------------------------------------------------------------------
extern "C" void kernel_launch(void* const* d_in, const int* in_sizes, int n_in,
                              void* d_out, int out_size)
{
    (void)in_sizes; (void)n_in; (void)out_size;

    const float* x     = (const float*)d_in[0];
    const float* Wih0f = (const float*)d_in[1];
    const float* Whh0f = (const float*)d_in[2];
    const float* bih0f = (const float*)d_in[3];
    const float* bhh0f = (const float*)d_in[4];
    const float* Wih0b = (const float*)d_in[5];
    const float* Whh0b = (const float*)d_in[6];
    const float* bih0b = (const float*)d_in[7];
    const float* bhh0b = (const float*)d_in[8];
    const float* Wih1f = (const float*)d_in[9];
    const float* Whh1f = (const float*)d_in[10];
    const float* bih1f = (const float*)d_in[11];
    const float* bhh1f = (const float*)d_in[12];
    const float* Wih1b = (const float*)d_in[13];
    const float* Whh1b = (const float*)d_in[14];
    const float* bih1b = (const float*)d_in[15];
    const float* bhh1b = (const float*)d_in[16];

    float* out = (float*)d_out;
    const size_t Y_ELEMS = (size_t)TT * BB * 1024;
    float* hid0 = out + Y_ELEMS;
    float* hid1 = out + Y_ELEMS + 2 * BB * HH;

    float* gi = nullptr; cudaGetSymbolAddress((void**)&gi, g_gi);
    __half* hf = nullptr; cudaGetSymbolAddress((void**)&hf, g_hf);
    unsigned* cnt  = nullptr; cudaGetSymbolAddress((void**)&cnt, g_cnt);
    unsigned* flag = nullptr; cudaGetSymbolAddress((void**)&flag, g_flag);
    __nv_bfloat16* wh = nullptr; cudaGetSymbolAddress((void**)&wh, g_wh);
    __nv_bfloat16* wl = nullptr; cudaGetSymbolAddress((void**)&wl, g_wl);
    __nv_bfloat16* xh = nullptr; cudaGetSymbolAddress((void**)&xh, g_xh);
    __nv_bfloat16* xl = nullptr; cudaGetSymbolAddress((void**)&xl, g_xl);

    cudaFuncSetAttribute(gru_layer_mma,
                         cudaFuncAttributeMaxDynamicSharedMemorySize, MMA_SMEM);
    cudaFuncSetAttribute(gemm_bf16_mma,
                         cudaFuncAttributeMaxDynamicSharedMemorySize, GEMM_SMEM);

    const size_t M = (size_t)TT * BB;            // 16384
    const size_t DIROFF = (size_t)1536 * M;
    const size_t WSLAB = (size_t)1536 * 1024;
    const dim3 ggrid(128, 12);
    const size_t HBYTES = (size_t)2 * 2 * BB * HH * sizeof(__half);

    // ---------------- layer 0 (K = 512) ----------------
    split_bf16<<<512, 256>>>(Wih0f, wh,          wl,          (size_t)1536 * DD);
    split_bf16<<<512, 256>>>(Wih0b, wh + WSLAB,  wl + WSLAB,  (size_t)1536 * DD);
    split_bf16<<<1024, 256>>>(x,    xh,          xl,          M * DD);

    gemm_bf16_mma<<<ggrid, 256, GEMM_SMEM>>>(wh,         wl,         xh, xl, bih0f,
                                             gi,          DD, (int)M);
    gemm_bf16_mma<<<ggrid, 256, GEMM_SMEM>>>(wh + WSLAB, wl + WSLAB, xh, xl, bih0b,
                                             gi + DIROFF, DD, (int)M);

    cudaMemsetAsync(hf, 0, HBYTES);
    cudaMemsetAsync(cnt, 0, 2 * sizeof(unsigned));
    cudaMemsetAsync(flag, 0, 2 * sizeof(unsigned));

    // layer-0 recurrence writes bf16 hi/lo X (K=1024 layout) directly.
    // Reuse of xh/xl is safe: layer-0 GEMMs have completed (stream order).
    gru_layer_mma<<<128, 128, MMA_SMEM>>>(
        gi, Whh0f, Whh0b, bhh0f, bhh0b, hf, cnt, flag,
        nullptr, xh, xl, 1024, hid0);

    // ---------------- layer 1 (K = 1024) ----------------
    split_bf16<<<512, 256>>>(Wih1f, wh,          wl,          (size_t)1536 * 1024);
    split_bf16<<<512, 256>>>(Wih1b, wh + WSLAB,  wl + WSLAB,  (size_t)1536 * 1024);

    gemm_bf16_mma<<<ggrid, 256, GEMM_SMEM>>>(wh,         wl,         xh, xl, bih1f,
                                             gi,          1024, (int)M);
    gemm_bf16_mma<<<ggrid, 256, GEMM_SMEM>>>(wh + WSLAB, wl + WSLAB, xh, xl, bih1b,
                                             gi + DIROFF, 1024, (int)M);

    cudaMemsetAsync(hf, 0, HBYTES);
    cudaMemsetAsync(cnt, 0, 2 * sizeof(unsigned));
    cudaMemsetAsync(flag, 0, 2 * sizeof(unsigned));

    gru_layer_mma<<<128, 128, MMA_SMEM>>>(
        gi, Whh1f, Whh1b, bhh1f, bhh1b, hf, cnt, flag,
        out, nullptr, nullptr, 0, hid1);
}

// round 16
// speedup vs baseline: 2.0447x; 1.1934x over previous
#include <cuda_runtime.h>
#include <cuda_bf16.h>
#include <cuda_fp16.h>
#include <cstdint>
#include <cstddef>

typedef unsigned long long ull;

// Problem constants
#define TT 512
#define BB 32
#define DD 512
#define HH 512

// ---------------------------------------------------------------------------
// Scratch (device globals — no allocations allowed)
// ---------------------------------------------------------------------------
__device__ float g_gi[(size_t)2 * 1536 * (TT * BB)];
// hidden state fp16 ping-pong: [2 buf][2 dir][32 b][512 k]
__device__ __half g_hf[2 * 2 * BB * HH];
__device__ unsigned g_cnt[2];
__device__ unsigned g_flag[2];
// fp16 GEMM operands
__device__ __half g_wf[2][1536 * 1024];            // Wih fp16, per dir
__device__ __half g_xf[(size_t)16384 * 1024];      // X fp16

// ---------------------------------------------------------------------------
// MMA / ldmatrix macros
// ---------------------------------------------------------------------------
#define MMA_F16(d, a, b) \
    asm volatile("mma.sync.aligned.m16n8k16.row.col.f32.f16.f16.f32 " \
        "{%0,%1,%2,%3}, {%4,%5,%6,%7}, {%8,%9}, {%0,%1,%2,%3};" \
        : "+f"((d)[0]), "+f"((d)[1]), "+f"((d)[2]), "+f"((d)[3]) \
        : "r"((a)[0]), "r"((a)[1]), "r"((a)[2]), "r"((a)[3]), \
          "r"((b)[0]), "r"((b)[1]))

#define LDSM_X4(r, addr) \
    asm volatile("ldmatrix.sync.aligned.m8n8.x4.shared.b16 {%0,%1,%2,%3}, [%4];" \
        : "=r"((r)[0]), "=r"((r)[1]), "=r"((r)[2]), "=r"((r)[3]) : "r"(addr))

#define LDSM_X2(r, addr) \
    asm volatile("ldmatrix.sync.aligned.m8n8.x2.shared.b16 {%0,%1}, [%2];" \
        : "=r"((r)[0]), "=r"((r)[1]) : "r"(addr))

#define CP_ASYNC16(dst, src) \
    asm volatile("cp.async.cg.shared.global [%0], [%1], 16;" \
        :: "r"(dst), "l"(src) : "memory")

// ---------------------------------------------------------------------------
// split fp32 -> fp16
// ---------------------------------------------------------------------------
__global__ void split_f16(const float* __restrict__ x,
                          __half* __restrict__ o, size_t n)
{
    size_t i = (size_t)blockIdx.x * blockDim.x + threadIdx.x;
    size_t stride = (size_t)gridDim.x * blockDim.x;
    for (; i < n; i += stride) {
        o[i] = __float2half(x[i]);
    }
}

// ---------------------------------------------------------------------------
// fp16 single-pass mma.sync GEMM, 2-stage cp.async pipelined.
// C[n][m] = sum_k W[n][k] * X[m][k] + bias[n],  ldc = M = 16384.
// Grid (m_tiles=128, n_tiles), 256 threads (8 warps, 2x4). BK=32.
// Dynamic smem: 2 stages x 2 tiles x 128 x SKW fp16 = 40,960 B.
// ---------------------------------------------------------------------------
#define SKW 40
#define TILE_E (128 * SKW)
#define STAGE_E (2 * TILE_E)
#define GEMM_SMEM (2 * STAGE_E * 2)

__global__ void __launch_bounds__(256)
gemm_f16_mma(const __half* __restrict__ Wf,
             const __half* __restrict__ Xf,
             const float* __restrict__ bias,
             float* __restrict__ C, int K, int ldc)
{
    extern __shared__ __align__(16) __half sm[];

    const int tid  = threadIdx.x;
    const int wid  = tid >> 5;
    const int lane = tid & 31;
    const int m0   = blockIdx.x * 128;
    const int n0   = blockIdx.y * 128;
    const int wn   = wid >> 2;
    const int wm   = wid & 3;

    float acc[4][4][4];
#pragma unroll
    for (int nt = 0; nt < 4; nt++)
#pragma unroll
        for (int mt = 0; mt < 4; mt++)
#pragma unroll
            for (int e = 0; e < 4; e++) acc[nt][mt][e] = 0.0f;

    const int a_off = (wn * 64 + (lane & 15)) * SKW + (lane >> 4) * 8;
    const int b_off = (wm * 32 + (lane & 7)) * SKW + ((lane >> 3) & 1) * 8;
    const uint32_t aW0 = (uint32_t)__cvta_generic_to_shared(sm + a_off);
    const uint32_t aX0 = (uint32_t)__cvta_generic_to_shared(sm + TILE_E + b_off);

    const int srow0 = tid >> 2, sc0 = tid & 3;
    const int srow1 = (tid + 256) >> 2, sc1 = (tid + 256) & 3;
    const uint32_t d00 = (uint32_t)__cvta_generic_to_shared(sm + srow0 * SKW + sc0 * 8);
    const uint32_t d01 = (uint32_t)__cvta_generic_to_shared(sm + srow1 * SKW + sc1 * 8);

    const int nk = K >> 5;

    // prologue: stage k-tile 0
    {
        const size_t gw0 = (size_t)(n0 + srow0) * K + sc0 * 8;
        const size_t gw1 = (size_t)(n0 + srow1) * K + sc1 * 8;
        const size_t gx0 = (size_t)(m0 + srow0) * K + sc0 * 8;
        const size_t gx1 = (size_t)(m0 + srow1) * K + sc1 * 8;
        CP_ASYNC16(d00,              Wf + gw0);
        CP_ASYNC16(d00 + TILE_E * 2, Xf + gx0);
        CP_ASYNC16(d01,              Wf + gw1);
        CP_ASYNC16(d01 + TILE_E * 2, Xf + gx1);
        asm volatile("cp.async.commit_group;" ::: "memory");
    }

    for (int kt = 0; kt < nk; kt++) {
        const uint32_t stB = (uint32_t)((kt & 1) * STAGE_E * 2);

        if (kt + 1 < nk) {
            const uint32_t nsB = (uint32_t)(((kt + 1) & 1) * STAGE_E * 2);
            const int k0n = (kt + 1) * 32;
            const size_t gw0 = (size_t)(n0 + srow0) * K + k0n + sc0 * 8;
            const size_t gw1 = (size_t)(n0 + srow1) * K + k0n + sc1 * 8;
            const size_t gx0 = (size_t)(m0 + srow0) * K + k0n + sc0 * 8;
            const size_t gx1 = (size_t)(m0 + srow1) * K + k0n + sc1 * 8;
            CP_ASYNC16(d00 + nsB,              Wf + gw0);
            CP_ASYNC16(d00 + nsB + TILE_E * 2, Xf + gx0);
            CP_ASYNC16(d01 + nsB,              Wf + gw1);
            CP_ASYNC16(d01 + nsB + TILE_E * 2, Xf + gx1);
            asm volatile("cp.async.commit_group;" ::: "memory");
            asm volatile("cp.async.wait_group 1;" ::: "memory");
        } else {
            asm volatile("cp.async.wait_group 0;" ::: "memory");
        }
        __syncthreads();

#pragma unroll
        for (int kk = 0; kk < 2; kk++) {
            const uint32_t koff = stB + (uint32_t)(kk * 32);
            uint32_t af[4][4], bf[4][2];
#pragma unroll
            for (int nt = 0; nt < 4; nt++) {
                const uint32_t ro = (uint32_t)(nt * 16 * SKW * 2);
                LDSM_X4(af[nt], aW0 + ro + koff);
            }
#pragma unroll
            for (int mt = 0; mt < 4; mt++) {
                const uint32_t ro = (uint32_t)(mt * 8 * SKW * 2);
                LDSM_X2(bf[mt], aX0 + ro + koff);
            }
#pragma unroll
            for (int nt = 0; nt < 4; nt++)
#pragma unroll
                for (int mt = 0; mt < 4; mt++) {
                    MMA_F16(acc[nt][mt], af[nt], bf[mt]);
                }
        }
        __syncthreads();
    }

    const int r0 = lane >> 2;
    const int c0 = (lane & 3) * 2;
#pragma unroll
    for (int nt = 0; nt < 4; nt++) {
        const int nbase = n0 + wn * 64 + nt * 16;
        const float b0 = bias[nbase + r0];
        const float b1 = bias[nbase + 8 + r0];
#pragma unroll
        for (int mt = 0; mt < 4; mt++) {
            const int mbase = m0 + wm * 32 + mt * 8;
            float2 v0, v1;
            v0.x = acc[nt][mt][0] + b0; v0.y = acc[nt][mt][1] + b0;
            v1.x = acc[nt][mt][2] + b1; v1.y = acc[nt][mt][3] + b1;
            *(float2*)(C + (size_t)(nbase + r0) * ldc + mbase + c0) = v0;
            *(float2*)(C + (size_t)(nbase + 8 + r0) * ldc + mbase + c0) = v1;
        }
    }
}

// ---------------------------------------------------------------------------
// Persistent MMA GRU v7 (round-15 PASSING, unchanged except layer-0 now
// writes single fp16 X instead of bf16 hi/lo).
// Grid: 128 CTAs = 2 dirs x 64 j-blocks (8 j). 128 threads (4 warps).
// SMEM: A(fp16) 33,280 B + red 12,288 B = 45,568 B.
// ---------------------------------------------------------------------------
#define RS 520
#define NCD 64
#define A_ELEMS (32 * RS)                 // fp16 elems in A buffer
#define RED_OFF (A_ELEMS * 2)             // bytes
#define MMA_SMEM (RED_OFF + 4 * 2 * 3 * 32 * 16)

__global__ __launch_bounds__(128, 1)
void gru_layer_mma(const float* __restrict__ gi,
                   const float* __restrict__ Whh_f,
                   const float* __restrict__ Whh_b,
                   const float* __restrict__ bhh_f,
                   const float* __restrict__ bhh_b,
                   __half* __restrict__ hf,          // [2][2][32][512]
                   unsigned* __restrict__ cnt,
                   unsigned* __restrict__ flag,
                   float* __restrict__ y,            // fp32 out (layer 1) or null
                   __half* __restrict__ xf,          // layer 0: fp16 X out (or null)
                   int xldc,                         // X row stride (1024)
                   float* __restrict__ hid)          // [2][B][H]
{
    extern __shared__ __align__(16) char smraw[];
    __half* sA  = (__half*)smraw;                    // [32][RS]
    float* red = (float*)(smraw + RED_OFF);

    __half* sW = sA;                                 // W init aliases A region

    const int tid  = threadIdx.x;
    const int wid  = tid >> 5;
    const int lane = tid & 31;
    const int dir  = (int)(blockIdx.x >> 6);
    const int j0   = (int)(blockIdx.x & 63) * 8;

    const float* Whh = dir ? Whh_b : Whh_f;
    const float* bhh = dir ? bhh_b : bhh_f;

    // ---- stage Whh tile (24 rows x 512) fp16 into smem ----
    for (int i = tid; i < 24 * 128; i += 128) {
        int rr = i >> 7;
        int c4 = i & 127;
        int g = rr >> 3, jj = rr & 7;
        int grow = g * 512 + j0 + jj;
        float4 v = *(const float4*)(Whh + (size_t)grow * 512 + c4 * 4);
        int so = rr * RS + c4 * 4;
        sW[so + 0] = __float2half(v.x);
        sW[so + 1] = __float2half(v.y);
        sW[so + 2] = __float2half(v.z);
        sW[so + 3] = __float2half(v.w);
    }
    __syncthreads();

    // ---- hoist B fragments into registers: [8 kt][3 g][2] ----
    uint32_t bf[8][3][2];
    {
        const int brow = (lane & 7);
        const int bcol = ((lane >> 3) & 1) * 8;
#pragma unroll
        for (int kt = 0; kt < 8; kt++) {
            const uint32_t koff = (uint32_t)((wid * 8 + kt) * 32);
#pragma unroll
            for (int g = 0; g < 3; g++) {
                uint32_t ad = (uint32_t)__cvta_generic_to_shared(
                    sW + (g * 8 + brow) * RS + bcol) + koff;
                LDSM_X2(bf[kt][g], ad);
            }
        }
    }
    __syncthreads();   // W region dead; A buffer may now be written

    uint32_t aA[2];
#pragma unroll
    for (int mt = 0; mt < 2; mt++) {
        const int arow = mt * 16 + (lane & 15);
        const int acol = (lane >> 4) * 8;
        aA[mt] = (uint32_t)__cvta_generic_to_shared(sA + arow * RS + acol);
    }

    const int gm  = wid;
    const int b0  = gm * 16 + (lane >> 2);
    const int b1  = b0 + 8;
    const int j   = j0 + 2 * (lane & 3);

    const float br0 = bhh[j],          br1 = bhh[j + 1];
    const float bz0 = bhh[HH + j],     bz1 = bhh[HH + j + 1];
    const float bn0 = bhh[2 * HH + j], bn1 = bhh[2 * HH + j + 1];

    const float* gb[3][2];
#pragma unroll
    for (int g = 0; g < 3; g++) {
#pragma unroll
        for (int q = 0; q < 2; q++)
            gb[g][q] = gi + ((size_t)dir * 1536 + g * 512 + j + q) * (size_t)(TT * BB);
    }

    unsigned* mycnt  = cnt + dir;
    unsigned* myflag = flag + dir;

    float hp[4] = {0.0f, 0.0f, 0.0f, 0.0f};

    for (int s = 0; s < TT; s++) {
        const int t = dir ? (TT - 1 - s) : s;

        // ---- stage h fp16 for this step: 32 rows x 512 = 2048 uint4 ----
        {
            const uint4* src = (const uint4*)(hf + ((size_t)(s & 1) * 2 + dir) * (BB * HH));
#pragma unroll
            for (int i = 0; i < 16; i++) {
                int idx = tid + i * 128;
                int row = idx >> 6;
                int c8  = idx & 63;
                uint4 v = __ldcg(src + idx);
                *(uint4*)(sA + row * RS + c8 * 8) = v;
            }
        }
        __syncthreads();

        // ---- gi prefetch (warps 0/1) ----
        float pre[3][4];
        if (wid < 2) {
#pragma unroll
            for (int g = 0; g < 3; g++) {
                pre[g][0] = __ldcg(gb[g][0] + t * BB + b0);
                pre[g][1] = __ldcg(gb[g][1] + t * BB + b0);
                pre[g][2] = __ldcg(gb[g][0] + t * BB + b1);
                pre[g][3] = __ldcg(gb[g][1] + t * BB + b1);
            }
        }

        // ---- MMA over this warp's 8 ktiles (single fp16 pass) ----
        float acc[2][3][4];
#pragma unroll
        for (int mt = 0; mt < 2; mt++)
#pragma unroll
            for (int g = 0; g < 3; g++)
#pragma unroll
                for (int e = 0; e < 4; e++) acc[mt][g][e] = 0.0f;

#pragma unroll
        for (int kt = 0; kt < 8; kt++) {
            const uint32_t koff = (uint32_t)((wid * 8 + kt) * 32);
#pragma unroll
            for (int mt = 0; mt < 2; mt++) {
                uint32_t ah[4];
                LDSM_X4(ah, aA[mt] + koff);
#pragma unroll
                for (int g = 0; g < 3; g++) {
                    MMA_F16(acc[mt][g], ah, bf[kt][g]);
                }
            }
        }

        // ---- cross-warp K-reduction via smem ----
#pragma unroll
        for (int mt = 0; mt < 2; mt++)
#pragma unroll
            for (int g = 0; g < 3; g++) {
                float4 v;
                v.x = acc[mt][g][0]; v.y = acc[mt][g][1];
                v.z = acc[mt][g][2]; v.w = acc[mt][g][3];
                *(float4*)(red + (((wid * 2 + mt) * 3 + g) * 32 + lane) * 4) = v;
            }
        __syncthreads();

        // ---- gates + h publish (warps 0/1, m-tile = wid) ----
        float hn[4];
        if (wid < 2) {
            float tot[3][4];
#pragma unroll
            for (int g = 0; g < 3; g++) {
                float4 v0 = *(float4*)(red + (((0 * 2 + gm) * 3 + g) * 32 + lane) * 4);
                float4 v1 = *(float4*)(red + (((1 * 2 + gm) * 3 + g) * 32 + lane) * 4);
                float4 v2 = *(float4*)(red + (((2 * 2 + gm) * 3 + g) * 32 + lane) * 4);
                float4 v3 = *(float4*)(red + (((3 * 2 + gm) * 3 + g) * 32 + lane) * 4);
                tot[g][0] = ((v0.x + v1.x) + (v2.x + v3.x));
                tot[g][1] = ((v0.y + v1.y) + (v2.y + v3.y));
                tot[g][2] = ((v0.z + v1.z) + (v2.z + v3.z));
                tot[g][3] = ((v0.w + v1.w) + (v2.w + v3.w));
            }

            const float brj[2] = {br0, br1}, bzj[2] = {bz0, bz1}, bnj[2] = {bn0, bn1};
#pragma unroll
            for (int c = 0; c < 4; c++) {
                const int q = c & 1;
                const float ar = tot[0][c] + brj[q];
                const float az = tot[1][c] + bzj[q];
                const float an = tot[2][c] + bnj[q];
                const float r = 1.0f / (1.0f + expf(-(pre[0][c] + ar)));
                const float z = 1.0f / (1.0f + expf(-(pre[1][c] + az)));
                const float n = tanhf(pre[2][c] + r * an);
                hn[c] = (1.0f - z) * n + z * hp[c];
                hp[c] = hn[c];
            }

            // publish h (fp16, ping-pong slot (s+1)&1) — critical path
            const size_t ob = ((size_t)((s + 1) & 1) * 2 + dir) * (BB * HH);
            *(__half2*)(hf + ob + (size_t)b0 * HH + j) =
                __floats2half2_rn(hn[0], hn[1]);
            *(__half2*)(hf + ob + (size_t)b1 * HH + j) =
                __floats2half2_rn(hn[2], hn[3]);
        }

        // ---- per-direction global barrier (proven) ----
        __syncthreads();
        if (tid == 0) {
            __threadfence();
            const unsigned target = (unsigned)(NCD * (s + 1));
            unsigned arrived = atomicAdd(mycnt, 1u) + 1u;
            if (arrived == target) {
                asm volatile("st.release.gpu.global.u32 [%0], %1;"
                             :: "l"(myflag), "r"((unsigned)(s + 1)) : "memory");
            }
        }

        // off-critical-path output stores while tid0 arrives/spins
        if (wid < 2) {
            if (xf) {
                // layer 0: write fp16 X for the layer-1 GEMM
                const size_t xb0 = ((size_t)t * BB + b0) * xldc + (size_t)dir * HH + j;
                const size_t xb1 = ((size_t)t * BB + b1) * xldc + (size_t)dir * HH + j;
                *(__half2*)(xf + xb0) = __floats2half2_rn(hn[0], hn[1]);
                *(__half2*)(xf + xb1) = __floats2half2_rn(hn[2], hn[3]);
            } else {
                float2 y2;
                y2.x = hn[0]; y2.y = hn[1];
                *(float2*)(y + ((size_t)t * BB + b0) * 1024 + (size_t)dir * HH + j) = y2;
                y2.x = hn[2]; y2.y = hn[3];
                *(float2*)(y + ((size_t)t * BB + b1) * 1024 + (size_t)dir * HH + j) = y2;
            }
            if (s == TT - 1) {
                float2 q2;
                q2.x = hn[0]; q2.y = hn[1];
                *(float2*)(hid + ((size_t)dir * BB + b0) * HH + j) = q2;
                q2.x = hn[2]; q2.y = hn[3];
                *(float2*)(hid + ((size_t)dir * BB + b1) * HH + j) = q2;
            }
        }

        if (tid == 0) {
            unsigned v;
            do {
                asm volatile("ld.acquire.gpu.global.u32 %0, [%1];"
                             : "=r"(v) : "l"(myflag) : "memory");
            } while (v < (unsigned)(s + 1));
            __threadfence();
        }
        __syncthreads();
    }
}

// ---------------------------------------------------------------------------
// Launch
// ---------------------------------------------------------------------------
extern "C" void kernel_launch(void* const* d_in, const int* in_sizes, int n_in,
                              void* d_out, int out_size)
{
    (void)in_sizes; (void)n_in; (void)out_size;

    const float* x     = (const float*)d_in[0];
    const float* Wih0f = (const float*)d_in[1];
    const float* Whh0f = (const float*)d_in[2];
    const float* bih0f = (const float*)d_in[3];
    const float* bhh0f = (const float*)d_in[4];
    const float* Wih0b = (const float*)d_in[5];
    const float* Whh0b = (const float*)d_in[6];
    const float* bih0b = (const float*)d_in[7];
    const float* bhh0b = (const float*)d_in[8];
    const float* Wih1f = (const float*)d_in[9];
    const float* Whh1f = (const float*)d_in[10];
    const float* bih1f = (const float*)d_in[11];
    const float* bhh1f = (const float*)d_in[12];
    const float* Wih1b = (const float*)d_in[13];
    const float* Whh1b = (const float*)d_in[14];
    const float* bih1b = (const float*)d_in[15];
    const float* bhh1b = (const float*)d_in[16];

    float* out = (float*)d_out;
    const size_t Y_ELEMS = (size_t)TT * BB * 1024;
    float* hid0 = out + Y_ELEMS;
    float* hid1 = out + Y_ELEMS + 2 * BB * HH;

    float* gi = nullptr; cudaGetSymbolAddress((void**)&gi, g_gi);
    __half* hf = nullptr; cudaGetSymbolAddress((void**)&hf, g_hf);
    unsigned* cnt  = nullptr; cudaGetSymbolAddress((void**)&cnt, g_cnt);
    unsigned* flag = nullptr; cudaGetSymbolAddress((void**)&flag, g_flag);
    __half* wf = nullptr; cudaGetSymbolAddress((void**)&wf, g_wf);
    __half* xf = nullptr; cudaGetSymbolAddress((void**)&xf, g_xf);

    cudaFuncSetAttribute(gru_layer_mma,
                         cudaFuncAttributeMaxDynamicSharedMemorySize, MMA_SMEM);
    cudaFuncSetAttribute(gemm_f16_mma,
                         cudaFuncAttributeMaxDynamicSharedMemorySize, GEMM_SMEM);

    const size_t M = (size_t)TT * BB;            // 16384
    const size_t DIROFF = (size_t)1536 * M;
    const size_t WSLAB = (size_t)1536 * 1024;    // per-dir W slab (fp16 elems)
    const dim3 ggrid(128, 12);
    const size_t HBYTES = (size_t)2 * 2 * BB * HH * sizeof(__half);

    // ---------------- layer 0 (K = 512) ----------------
    split_f16<<<512, 256>>>(Wih0f, wf,         (size_t)1536 * DD);
    split_f16<<<512, 256>>>(Wih0b, wf + WSLAB, (size_t)1536 * DD);
    split_f16<<<1024, 256>>>(x,    xf,          M * DD);

    gemm_f16_mma<<<ggrid, 256, GEMM_SMEM>>>(wf,         xf, bih0f,
                                            gi,          DD, (int)M);
    gemm_f16_mma<<<ggrid, 256, GEMM_SMEM>>>(wf + WSLAB, xf, bih0b,
                                            gi + DIROFF, DD, (int)M);

    cudaMemsetAsync(hf, 0, HBYTES);
    cudaMemsetAsync(cnt, 0, 2 * sizeof(unsigned));
    cudaMemsetAsync(flag, 0, 2 * sizeof(unsigned));

    // layer-0 recurrence writes fp16 X (K=1024 layout) directly into xf.
    // Safe: layer-0 GEMMs (the only readers of the old xf) complete first.
    gru_layer_mma<<<128, 128, MMA_SMEM>>>(
        gi, Whh0f, Whh0b, bhh0f, bhh0b, hf, cnt, flag,
        nullptr, xf, 1024, hid0);

    // ---------------- layer 1 (K = 1024) ----------------
    split_f16<<<512, 256>>>(Wih1f, wf,         (size_t)1536 * 1024);
    split_f16<<<512, 256>>>(Wih1b, wf + WSLAB, (size_t)1536 * 1024);

    gemm_f16_mma<<<ggrid, 256, GEMM_SMEM>>>(wf,         xf, bih1f,
                                            gi,          1024, (int)M);
    gemm_f16_mma<<<ggrid, 256, GEMM_SMEM>>>(wf + WSLAB, xf, bih1b,
                                            gi + DIROFF, 1024, (int)M);

    cudaMemsetAsync(hf, 0, HBYTES);
    cudaMemsetAsync(cnt, 0, 2 * sizeof(unsigned));
    cudaMemsetAsync(flag, 0, 2 * sizeof(unsigned));

    gru_layer_mma<<<128, 128, MMA_SMEM>>>(
        gi, Whh1f, Whh1b, bhh1f, bhh1b, hf, cnt, flag,
        out, nullptr, 0, hid1);
}

// round 17
// speedup vs baseline: 2.4068x; 1.1771x over previous
#include <cuda_runtime.h>
#include <cuda_bf16.h>
#include <cuda_fp16.h>
#include <cstdint>
#include <cstddef>

typedef unsigned long long ull;

// Problem constants
#define TT 512
#define BB 32
#define DD 512
#define HH 512

// ---------------------------------------------------------------------------
// Scratch (device globals — no allocations allowed)
// ---------------------------------------------------------------------------
__device__ float g_gi[(size_t)2 * 1536 * (TT * BB)];
// hidden state fp16 ping-pong: [2 buf][2 dir][32 b][512 k]
__device__ __half g_hf[2 * 2 * BB * HH];
__device__ unsigned g_cnt[2];
// fp16 GEMM operands
__device__ __half g_wf[2][1536 * 1024];            // Wih fp16, per dir
__device__ __half g_xf[(size_t)16384 * 1024];      // X fp16

// ---------------------------------------------------------------------------
// MMA / ldmatrix macros
// ---------------------------------------------------------------------------
#define MMA_F16(d, a, b) \
    asm volatile("mma.sync.aligned.m16n8k16.row.col.f32.f16.f16.f32 " \
        "{%0,%1,%2,%3}, {%4,%5,%6,%7}, {%8,%9}, {%0,%1,%2,%3};" \
        : "+f"((d)[0]), "+f"((d)[1]), "+f"((d)[2]), "+f"((d)[3]) \
        : "r"((a)[0]), "r"((a)[1]), "r"((a)[2]), "r"((a)[3]), \
          "r"((b)[0]), "r"((b)[1]))

#define LDSM_X4(r, addr) \
    asm volatile("ldmatrix.sync.aligned.m8n8.x4.shared.b16 {%0,%1,%2,%3}, [%4];" \
        : "=r"((r)[0]), "=r"((r)[1]), "=r"((r)[2]), "=r"((r)[3]) : "r"(addr))

#define LDSM_X2(r, addr) \
    asm volatile("ldmatrix.sync.aligned.m8n8.x2.shared.b16 {%0,%1}, [%2];" \
        : "=r"((r)[0]), "=r"((r)[1]) : "r"(addr))

#define CP_ASYNC16(dst, src) \
    asm volatile("cp.async.cg.shared.global [%0], [%1], 16;" \
        :: "r"(dst), "l"(src) : "memory")

// ---------------------------------------------------------------------------
// split fp32 -> fp16
// ---------------------------------------------------------------------------
__global__ void split_f16(const float* __restrict__ x,
                          __half* __restrict__ o, size_t n)
{
    size_t i = (size_t)blockIdx.x * blockDim.x + threadIdx.x;
    size_t stride = (size_t)gridDim.x * blockDim.x;
    for (; i < n; i += stride) {
        o[i] = __float2half(x[i]);
    }
}

// ---------------------------------------------------------------------------
// fp16 single-pass mma.sync GEMM, 2-stage cp.async (round-16 passing).
// ---------------------------------------------------------------------------
#define SKW 40
#define TILE_E (128 * SKW)
#define STAGE_E (2 * TILE_E)
#define GEMM_SMEM (2 * STAGE_E * 2)

__global__ void __launch_bounds__(256)
gemm_f16_mma(const __half* __restrict__ Wf,
             const __half* __restrict__ Xf,
             const float* __restrict__ bias,
             float* __restrict__ C, int K, int ldc)
{
    extern __shared__ __align__(16) __half sm[];

    const int tid  = threadIdx.x;
    const int wid  = tid >> 5;
    const int lane = tid & 31;
    const int m0   = blockIdx.x * 128;
    const int n0   = blockIdx.y * 128;
    const int wn   = wid >> 2;
    const int wm   = wid & 3;

    float acc[4][4][4];
#pragma unroll
    for (int nt = 0; nt < 4; nt++)
#pragma unroll
        for (int mt = 0; mt < 4; mt++)
#pragma unroll
            for (int e = 0; e < 4; e++) acc[nt][mt][e] = 0.0f;

    const int a_off = (wn * 64 + (lane & 15)) * SKW + (lane >> 4) * 8;
    const int b_off = (wm * 32 + (lane & 7)) * SKW + ((lane >> 3) & 1) * 8;
    const uint32_t aW0 = (uint32_t)__cvta_generic_to_shared(sm + a_off);
    const uint32_t aX0 = (uint32_t)__cvta_generic_to_shared(sm + TILE_E + b_off);

    const int srow0 = tid >> 2, sc0 = tid & 3;
    const int srow1 = (tid + 256) >> 2, sc1 = (tid + 256) & 3;
    const uint32_t d00 = (uint32_t)__cvta_generic_to_shared(sm + srow0 * SKW + sc0 * 8);
    const uint32_t d01 = (uint32_t)__cvta_generic_to_shared(sm + srow1 * SKW + sc1 * 8);

    const int nk = K >> 5;

    {
        const size_t gw0 = (size_t)(n0 + srow0) * K + sc0 * 8;
        const size_t gw1 = (size_t)(n0 + srow1) * K + sc1 * 8;
        const size_t gx0 = (size_t)(m0 + srow0) * K + sc0 * 8;
        const size_t gx1 = (size_t)(m0 + srow1) * K + sc1 * 8;
        CP_ASYNC16(d00,              Wf + gw0);
        CP_ASYNC16(d00 + TILE_E * 2, Xf + gx0);
        CP_ASYNC16(d01,              Wf + gw1);
        CP_ASYNC16(d01 + TILE_E * 2, Xf + gx1);
        asm volatile("cp.async.commit_group;" ::: "memory");
    }

    for (int kt = 0; kt < nk; kt++) {
        const uint32_t stB = (uint32_t)((kt & 1) * STAGE_E * 2);

        if (kt + 1 < nk) {
            const uint32_t nsB = (uint32_t)(((kt + 1) & 1) * STAGE_E * 2);
            const int k0n = (kt + 1) * 32;
            const size_t gw0 = (size_t)(n0 + srow0) * K + k0n + sc0 * 8;
            const size_t gw1 = (size_t)(n0 + srow1) * K + k0n + sc1 * 8;
            const size_t gx0 = (size_t)(m0 + srow0) * K + k0n + sc0 * 8;
            const size_t gx1 = (size_t)(m0 + srow1) * K + k0n + sc1 * 8;
            CP_ASYNC16(d00 + nsB,              Wf + gw0);
            CP_ASYNC16(d00 + nsB + TILE_E * 2, Xf + gx0);
            CP_ASYNC16(d01 + nsB,              Wf + gw1);
            CP_ASYNC16(d01 + nsB + TILE_E * 2, Xf + gx1);
            asm volatile("cp.async.commit_group;" ::: "memory");
            asm volatile("cp.async.wait_group 1;" ::: "memory");
        } else {
            asm volatile("cp.async.wait_group 0;" ::: "memory");
        }
        __syncthreads();

#pragma unroll
        for (int kk = 0; kk < 2; kk++) {
            const uint32_t koff = stB + (uint32_t)(kk * 32);
            uint32_t af[4][4], bfr[4][2];
#pragma unroll
            for (int nt = 0; nt < 4; nt++) {
                const uint32_t ro = (uint32_t)(nt * 16 * SKW * 2);
                LDSM_X4(af[nt], aW0 + ro + koff);
            }
#pragma unroll
            for (int mt = 0; mt < 4; mt++) {
                const uint32_t ro = (uint32_t)(mt * 8 * SKW * 2);
                LDSM_X2(bfr[mt], aX0 + ro + koff);
            }
#pragma unroll
            for (int nt = 0; nt < 4; nt++)
#pragma unroll
                for (int mt = 0; mt < 4; mt++) {
                    MMA_F16(acc[nt][mt], af[nt], bfr[mt]);
                }
        }
        __syncthreads();
    }

    const int r0 = lane >> 2;
    const int c0 = (lane & 3) * 2;
#pragma unroll
    for (int nt = 0; nt < 4; nt++) {
        const int nbase = n0 + wn * 64 + nt * 16;
        const float b0 = bias[nbase + r0];
        const float b1 = bias[nbase + 8 + r0];
#pragma unroll
        for (int mt = 0; mt < 4; mt++) {
            const int mbase = m0 + wm * 32 + mt * 8;
            float2 v0, v1;
            v0.x = acc[nt][mt][0] + b0; v0.y = acc[nt][mt][1] + b0;
            v1.x = acc[nt][mt][2] + b1; v1.y = acc[nt][mt][3] + b1;
            *(float2*)(C + (size_t)(nbase + r0) * ldc + mbase + c0) = v0;
            *(float2*)(C + (size_t)(nbase + 8 + r0) * ldc + mbase + c0) = v1;
        }
    }
}

// ---------------------------------------------------------------------------
// Persistent MMA GRU v8: round-16 engine + BARRIER v2.
// Arrivals via red.release.gpu.add (REDG: pipelined, no same-address atomic
// serialization, release carries h stores -> no membar). ALL CTAs spin
// directly on the counter with ld.acquire (no flag hop). 64 pollers/word
// at ~1 req / 300cyc — far below contention regimes seen in r9/r14.
// Grid: 128 CTAs = 2 dirs x 64 j-blocks (8 j). 128 threads (4 warps).
// SMEM: A(fp16) 33,280 B + red 12,288 B = 45,568 B.
// ---------------------------------------------------------------------------
#define RS 520
#define NCD 64
#define A_ELEMS (32 * RS)                 // fp16 elems in A buffer
#define RED_OFF (A_ELEMS * 2)             // bytes
#define MMA_SMEM (RED_OFF + 4 * 2 * 3 * 32 * 16)

__global__ __launch_bounds__(128, 1)
void gru_layer_mma(const float* __restrict__ gi,
                   const float* __restrict__ Whh_f,
                   const float* __restrict__ Whh_b,
                   const float* __restrict__ bhh_f,
                   const float* __restrict__ bhh_b,
                   __half* __restrict__ hf,          // [2][2][32][512]
                   unsigned* __restrict__ cnt,       // [2], zeroed pre-launch
                   float* __restrict__ y,            // fp32 out (layer 1) or null
                   __half* __restrict__ xf,          // layer 0: fp16 X out (or null)
                   int xldc,                         // X row stride (1024)
                   float* __restrict__ hid)          // [2][B][H]
{
    extern __shared__ __align__(16) char smraw[];
    __half* sA  = (__half*)smraw;                    // [32][RS]
    float* red = (float*)(smraw + RED_OFF);

    __half* sW = sA;                                 // W init aliases A region

    const int tid  = threadIdx.x;
    const int wid  = tid >> 5;
    const int lane = tid & 31;
    const int dir  = (int)(blockIdx.x >> 6);
    const int j0   = (int)(blockIdx.x & 63) * 8;

    const float* Whh = dir ? Whh_b : Whh_f;
    const float* bhh = dir ? bhh_b : bhh_f;

    // ---- stage Whh tile (24 rows x 512) fp16 into smem ----
    for (int i = tid; i < 24 * 128; i += 128) {
        int rr = i >> 7;
        int c4 = i & 127;
        int g = rr >> 3, jj = rr & 7;
        int grow = g * 512 + j0 + jj;
        float4 v = *(const float4*)(Whh + (size_t)grow * 512 + c4 * 4);
        int so = rr * RS + c4 * 4;
        sW[so + 0] = __float2half(v.x);
        sW[so + 1] = __float2half(v.y);
        sW[so + 2] = __float2half(v.z);
        sW[so + 3] = __float2half(v.w);
    }
    __syncthreads();

    // ---- hoist B fragments into registers: [8 kt][3 g][2] ----
    uint32_t bf[8][3][2];
    {
        const int brow = (lane & 7);
        const int bcol = ((lane >> 3) & 1) * 8;
#pragma unroll
        for (int kt = 0; kt < 8; kt++) {
            const uint32_t koff = (uint32_t)((wid * 8 + kt) * 32);
#pragma unroll
            for (int g = 0; g < 3; g++) {
                uint32_t ad = (uint32_t)__cvta_generic_to_shared(
                    sW + (g * 8 + brow) * RS + bcol) + koff;
                LDSM_X2(bf[kt][g], ad);
            }
        }
    }
    __syncthreads();   // W region dead; A buffer may now be written

    uint32_t aA[2];
#pragma unroll
    for (int mt = 0; mt < 2; mt++) {
        const int arow = mt * 16 + (lane & 15);
        const int acol = (lane >> 4) * 8;
        aA[mt] = (uint32_t)__cvta_generic_to_shared(sA + arow * RS + acol);
    }

    const int gm  = wid;
    const int b0  = gm * 16 + (lane >> 2);
    const int b1  = b0 + 8;
    const int j   = j0 + 2 * (lane & 3);

    const float br0 = bhh[j],          br1 = bhh[j + 1];
    const float bz0 = bhh[HH + j],     bz1 = bhh[HH + j + 1];
    const float bn0 = bhh[2 * HH + j], bn1 = bhh[2 * HH + j + 1];

    const float* gb[3][2];
#pragma unroll
    for (int g = 0; g < 3; g++) {
#pragma unroll
        for (int q = 0; q < 2; q++)
            gb[g][q] = gi + ((size_t)dir * 1536 + g * 512 + j + q) * (size_t)(TT * BB);
    }

    unsigned* mycnt = cnt + dir;

    float hp[4] = {0.0f, 0.0f, 0.0f, 0.0f};

    for (int s = 0; s < TT; s++) {
        const int t = dir ? (TT - 1 - s) : s;

        // ---- gi prefetch (warps 0/1) — issue BEFORE h staging ----
        float pre[3][4];
        if (wid < 2) {
#pragma unroll
            for (int g = 0; g < 3; g++) {
                pre[g][0] = __ldcg(gb[g][0] + t * BB + b0);
                pre[g][1] = __ldcg(gb[g][1] + t * BB + b0);
                pre[g][2] = __ldcg(gb[g][0] + t * BB + b1);
                pre[g][3] = __ldcg(gb[g][1] + t * BB + b1);
            }
        }

        // ---- stage h fp16 for this step: 32 rows x 512 = 2048 uint4 ----
        {
            const uint4* src = (const uint4*)(hf + ((size_t)(s & 1) * 2 + dir) * (BB * HH));
#pragma unroll
            for (int i = 0; i < 16; i++) {
                int idx = tid + i * 128;
                int row = idx >> 6;
                int c8  = idx & 63;
                uint4 v = __ldcg(src + idx);
                *(uint4*)(sA + row * RS + c8 * 8) = v;
            }
        }
        __syncthreads();

        // ---- MMA over this warp's 8 ktiles (single fp16 pass) ----
        float acc[2][3][4];
#pragma unroll
        for (int mt = 0; mt < 2; mt++)
#pragma unroll
            for (int g = 0; g < 3; g++)
#pragma unroll
                for (int e = 0; e < 4; e++) acc[mt][g][e] = 0.0f;

#pragma unroll
        for (int kt = 0; kt < 8; kt++) {
            const uint32_t koff = (uint32_t)((wid * 8 + kt) * 32);
#pragma unroll
            for (int mt = 0; mt < 2; mt++) {
                uint32_t ah[4];
                LDSM_X4(ah, aA[mt] + koff);
#pragma unroll
                for (int g = 0; g < 3; g++) {
                    MMA_F16(acc[mt][g], ah, bf[kt][g]);
                }
            }
        }

        // ---- cross-warp K-reduction via smem ----
#pragma unroll
        for (int mt = 0; mt < 2; mt++)
#pragma unroll
            for (int g = 0; g < 3; g++) {
                float4 v;
                v.x = acc[mt][g][0]; v.y = acc[mt][g][1];
                v.z = acc[mt][g][2]; v.w = acc[mt][g][3];
                *(float4*)(red + (((wid * 2 + mt) * 3 + g) * 32 + lane) * 4) = v;
            }
        __syncthreads();

        // ---- gates + h publish (warps 0/1, m-tile = wid) ----
        float hn[4];
        if (wid < 2) {
            float tot[3][4];
#pragma unroll
            for (int g = 0; g < 3; g++) {
                float4 v0 = *(float4*)(red + (((0 * 2 + gm) * 3 + g) * 32 + lane) * 4);
                float4 v1 = *(float4*)(red + (((1 * 2 + gm) * 3 + g) * 32 + lane) * 4);
                float4 v2 = *(float4*)(red + (((2 * 2 + gm) * 3 + g) * 32 + lane) * 4);
                float4 v3 = *(float4*)(red + (((3 * 2 + gm) * 3 + g) * 32 + lane) * 4);
                tot[g][0] = ((v0.x + v1.x) + (v2.x + v3.x));
                tot[g][1] = ((v0.y + v1.y) + (v2.y + v3.y));
                tot[g][2] = ((v0.z + v1.z) + (v2.z + v3.z));
                tot[g][3] = ((v0.w + v1.w) + (v2.w + v3.w));
            }

            const float brj[2] = {br0, br1}, bzj[2] = {bz0, bz1}, bnj[2] = {bn0, bn1};
#pragma unroll
            for (int c = 0; c < 4; c++) {
                const int q = c & 1;
                const float ar = tot[0][c] + brj[q];
                const float az = tot[1][c] + bzj[q];
                const float an = tot[2][c] + bnj[q];
                const float r = 1.0f / (1.0f + expf(-(pre[0][c] + ar)));
                const float z = 1.0f / (1.0f + expf(-(pre[1][c] + az)));
                const float n = tanhf(pre[2][c] + r * an);
                hn[c] = (1.0f - z) * n + z * hp[c];
                hp[c] = hn[c];
            }

            // publish h (fp16, ping-pong slot (s+1)&1) — critical path
            const size_t ob = ((size_t)((s + 1) & 1) * 2 + dir) * (BB * HH);
            *(__half2*)(hf + ob + (size_t)b0 * HH + j) =
                __floats2half2_rn(hn[0], hn[1]);
            *(__half2*)(hf + ob + (size_t)b1 * HH + j) =
                __floats2half2_rn(hn[2], hn[3]);
        }

        // ---- barrier v2: REDG release arrival + direct counter spin ----
        __syncthreads();       // all h stores issued CTA-wide
        if (tid == 0) {
            // release: orders this CTA's prior stores before the arrival
            asm volatile("red.release.gpu.global.add.u32 [%0], %1;"
                         :: "l"(mycnt), "r"(1u) : "memory");
        }

        // off-critical-path output stores while tid0 spins
        if (wid < 2) {
            if (xf) {
                const size_t xb0 = ((size_t)t * BB + b0) * xldc + (size_t)dir * HH + j;
                const size_t xb1 = ((size_t)t * BB + b1) * xldc + (size_t)dir * HH + j;
                *(__half2*)(xf + xb0) = __floats2half2_rn(hn[0], hn[1]);
                *(__half2*)(xf + xb1) = __floats2half2_rn(hn[2], hn[3]);
            } else {
                float2 y2;
                y2.x = hn[0]; y2.y = hn[1];
                *(float2*)(y + ((size_t)t * BB + b0) * 1024 + (size_t)dir * HH + j) = y2;
                y2.x = hn[2]; y2.y = hn[3];
                *(float2*)(y + ((size_t)t * BB + b1) * 1024 + (size_t)dir * HH + j) = y2;
            }
            if (s == TT - 1) {
                float2 q2;
                q2.x = hn[0]; q2.y = hn[1];
                *(float2*)(hid + ((size_t)dir * BB + b0) * HH + j) = q2;
                q2.x = hn[2]; q2.y = hn[3];
                *(float2*)(hid + ((size_t)dir * BB + b1) * HH + j) = q2;
            }
        }

        if (tid == 0) {
            const unsigned target = (unsigned)(NCD * (s + 1));
            unsigned v;
            do {
                asm volatile("ld.acquire.gpu.global.u32 %0, [%1];"
                             : "=r"(v) : "l"(mycnt) : "memory");
            } while (v < target);
        }
        __syncthreads();
    }
}

// ---------------------------------------------------------------------------
// Launch
// ---------------------------------------------------------------------------
extern "C" void kernel_launch(void* const* d_in, const int* in_sizes, int n_in,
                              void* d_out, int out_size)
{
    (void)in_sizes; (void)n_in; (void)out_size;

    const float* x     = (const float*)d_in[0];
    const float* Wih0f = (const float*)d_in[1];
    const float* Whh0f = (const float*)d_in[2];
    const float* bih0f = (const float*)d_in[3];
    const float* bhh0f = (const float*)d_in[4];
    const float* Wih0b = (const float*)d_in[5];
    const float* Whh0b = (const float*)d_in[6];
    const float* bih0b = (const float*)d_in[7];
    const float* bhh0b = (const float*)d_in[8];
    const float* Wih1f = (const float*)d_in[9];
    const float* Whh1f = (const float*)d_in[10];
    const float* bih1f = (const float*)d_in[11];
    const float* bhh1f = (const float*)d_in[12];
    const float* Wih1b = (const float*)d_in[13];
    const float* Whh1b = (const float*)d_in[14];
    const float* bih1b = (const float*)d_in[15];
    const float* bhh1b = (const float*)d_in[16];

    float* out = (float*)d_out;
    const size_t Y_ELEMS = (size_t)TT * BB * 1024;
    float* hid0 = out + Y_ELEMS;
    float* hid1 = out + Y_ELEMS + 2 * BB * HH;

    float* gi = nullptr; cudaGetSymbolAddress((void**)&gi, g_gi);
    __half* hf = nullptr; cudaGetSymbolAddress((void**)&hf, g_hf);
    unsigned* cnt  = nullptr; cudaGetSymbolAddress((void**)&cnt, g_cnt);
    __half* wf = nullptr; cudaGetSymbolAddress((void**)&wf, g_wf);
    __half* xf = nullptr; cudaGetSymbolAddress((void**)&xf, g_xf);

    cudaFuncSetAttribute(gru_layer_mma,
                         cudaFuncAttributeMaxDynamicSharedMemorySize, MMA_SMEM);
    cudaFuncSetAttribute(gemm_f16_mma,
                         cudaFuncAttributeMaxDynamicSharedMemorySize, GEMM_SMEM);

    const size_t M = (size_t)TT * BB;            // 16384
    const size_t DIROFF = (size_t)1536 * M;
    const size_t WSLAB = (size_t)1536 * 1024;    // per-dir W slab (fp16 elems)
    const dim3 ggrid(128, 12);
    const size_t HBYTES = (size_t)2 * 2 * BB * HH * sizeof(__half);

    // ---------------- layer 0 (K = 512) ----------------
    split_f16<<<512, 256>>>(Wih0f, wf,         (size_t)1536 * DD);
    split_f16<<<512, 256>>>(Wih0b, wf + WSLAB, (size_t)1536 * DD);
    split_f16<<<1024, 256>>>(x,    xf,          M * DD);

    gemm_f16_mma<<<ggrid, 256, GEMM_SMEM>>>(wf,         xf, bih0f,
                                            gi,          DD, (int)M);
    gemm_f16_mma<<<ggrid, 256, GEMM_SMEM>>>(wf + WSLAB, xf, bih0b,
                                            gi + DIROFF, DD, (int)M);

    cudaMemsetAsync(hf, 0, HBYTES);
    cudaMemsetAsync(cnt, 0, 2 * sizeof(unsigned));

    // layer-0 recurrence writes fp16 X (K=1024 layout) directly into xf.
    gru_layer_mma<<<128, 128, MMA_SMEM>>>(
        gi, Whh0f, Whh0b, bhh0f, bhh0b, hf, cnt,
        nullptr, xf, 1024, hid0);

    // ---------------- layer 1 (K = 1024) ----------------
    split_f16<<<512, 256>>>(Wih1f, wf,         (size_t)1536 * 1024);
    split_f16<<<512, 256>>>(Wih1b, wf + WSLAB, (size_t)1536 * 1024);

    gemm_f16_mma<<<ggrid, 256, GEMM_SMEM>>>(wf,         xf, bih1f,
                                            gi,          1024, (int)M);
    gemm_f16_mma<<<ggrid, 256, GEMM_SMEM>>>(wf + WSLAB, xf, bih1b,
                                            gi + DIROFF, 1024, (int)M);

    cudaMemsetAsync(hf, 0, HBYTES);
    cudaMemsetAsync(cnt, 0, 2 * sizeof(unsigned));

    gru_layer_mma<<<128, 128, MMA_SMEM>>>(
        gi, Whh1f, Whh1b, bhh1f, bhh1b, hf, cnt,
        out, nullptr, 0, hid1);
}